// round 4
// baseline (speedup 1.0000x reference)
#include <cuda_runtime.h>
#include <math.h>

// ---------------------------------------------------------------------------
// Problem constants
// ---------------------------------------------------------------------------
#define DM     1024
#define L_SEQ  2048
#define BATCH  4
#define NROWS  (BATCH * L_SEQ)   // 8192
#define NH     16
#define DH     64
#define FFH    2048

// ---------------------------------------------------------------------------
// Scratch (device globals: allocation-free per harness rules)
// ---------------------------------------------------------------------------
__device__ float g_h  [(size_t)NROWS * DM];       // 32 MB  (LN outputs)
__device__ float g_qkv[(size_t)NROWS * 3 * DM];   // 96 MB
__device__ float g_ctx[(size_t)NROWS * DM];       // 32 MB
__device__ float g_ffh[(size_t)NROWS * FFH];      // 64 MB

// ---------------------------------------------------------------------------
// LayerNorm: one block per row of 1024, 256 threads, float4 per thread
// ---------------------------------------------------------------------------
__global__ void ln_kernel(const float* __restrict__ x,
                          const float* __restrict__ gam,
                          const float* __restrict__ bet,
                          float* __restrict__ out)
{
    const int row = blockIdx.x;
    const int t   = threadIdx.x;
    const float4 v = reinterpret_cast<const float4*>(x + (size_t)row * DM)[t];

    float s  = v.x + v.y + v.z + v.w;
    float ss = v.x*v.x + v.y*v.y + v.z*v.z + v.w*v.w;

    __shared__ float rs[8], rq[8];
    #pragma unroll
    for (int m = 16; m > 0; m >>= 1) {
        s  += __shfl_down_sync(0xffffffffu, s,  m);
        ss += __shfl_down_sync(0xffffffffu, ss, m);
    }
    if ((t & 31) == 0) { rs[t >> 5] = s; rq[t >> 5] = ss; }
    __syncthreads();
    if (t == 0) {
        float a = 0.f, b = 0.f;
        #pragma unroll
        for (int i = 0; i < 8; i++) { a += rs[i]; b += rq[i]; }
        rs[0] = a; rq[0] = b;
    }
    __syncthreads();

    const float mean = rs[0] * (1.0f / DM);
    const float var  = rq[0] * (1.0f / DM) - mean * mean;
    const float rstd = rsqrtf(var + 1e-5f);

    const float4 g4 = reinterpret_cast<const float4*>(gam)[t];
    const float4 b4 = reinterpret_cast<const float4*>(bet)[t];
    float4 o;
    o.x = (v.x - mean) * rstd * g4.x + b4.x;
    o.y = (v.y - mean) * rstd * g4.y + b4.y;
    o.z = (v.z - mean) * rstd * g4.z + b4.z;
    o.w = (v.w - mean) * rstd * g4.w + b4.w;
    reinterpret_cast<float4*>(out + (size_t)row * DM)[t] = o;
}

// ---------------------------------------------------------------------------
// SGEMM: C[M,N] = A[M,K] @ B[K,N] (+bias, optional GELU / residual)
// 128x128 block tile, Ktile=8, 256 threads, 8x8 microtile, reg prefetch.
// EPI: 0 = +bias, 1 = +bias then exact GELU, 2 = +bias +residual
// M,N,K all multiples of 128/8 for this problem (no bounds checks).
// ---------------------------------------------------------------------------
template<int EPI>
__global__ __launch_bounds__(256)
void sgemm_kernel(const float* __restrict__ A, const float* __restrict__ B,
                  const float* __restrict__ bias, const float* __restrict__ res,
                  float* __restrict__ C, int M, int N, int K)
{
    __shared__ float As[8][132];   // A^T tile: As[k][m], pad 132 -> conflict-free stores
    __shared__ float Bs[8][128];   // B tile row-major

    const int tid = threadIdx.x;
    const int bm  = blockIdx.y, bn = blockIdx.x;
    const int ty  = tid >> 4, tx = tid & 15;

    const int arow = tid >> 1,  acol = (tid & 1) << 2;   // 128 rows x 2 float4
    const int brow = tid >> 5,  bcol = (tid & 31) << 2;  // 8 rows x 32 float4

    const float* Ap = A + (size_t)(bm * 128 + arow) * K + acol;
    const float* Bp = B + (size_t)brow * N + bn * 128 + bcol;

    float4 pa = *reinterpret_cast<const float4*>(Ap);
    float4 pb = *reinterpret_cast<const float4*>(Bp);

    float acc[8][8];
    #pragma unroll
    for (int i = 0; i < 8; i++)
        #pragma unroll
        for (int j = 0; j < 8; j++) acc[i][j] = 0.f;

    const int ktiles = K >> 3;
    for (int kt = 0; kt < ktiles; ++kt) {
        As[acol + 0][arow] = pa.x;
        As[acol + 1][arow] = pa.y;
        As[acol + 2][arow] = pa.z;
        As[acol + 3][arow] = pa.w;
        *reinterpret_cast<float4*>(&Bs[brow][bcol]) = pb;
        __syncthreads();

        if (kt + 1 < ktiles) {
            pa = *reinterpret_cast<const float4*>(Ap + (kt + 1) * 8);
            pb = *reinterpret_cast<const float4*>(Bp + (size_t)(kt + 1) * 8 * N);
        }

        #pragma unroll
        for (int k = 0; k < 8; k++) {
            float a[8], b[8];
            *reinterpret_cast<float4*>(&a[0]) = *reinterpret_cast<const float4*>(&As[k][ty * 4]);
            *reinterpret_cast<float4*>(&a[4]) = *reinterpret_cast<const float4*>(&As[k][ty * 4 + 64]);
            *reinterpret_cast<float4*>(&b[0]) = *reinterpret_cast<const float4*>(&Bs[k][tx * 4]);
            *reinterpret_cast<float4*>(&b[4]) = *reinterpret_cast<const float4*>(&Bs[k][tx * 4 + 64]);
            #pragma unroll
            for (int i = 0; i < 8; i++)
                #pragma unroll
                for (int j = 0; j < 8; j++)
                    acc[i][j] = fmaf(a[i], b[j], acc[i][j]);
        }
        __syncthreads();
    }

    // epilogue
    #pragma unroll
    for (int ii = 0; ii < 2; ii++) {
        #pragma unroll
        for (int i = 0; i < 4; i++) {
            const int r = bm * 128 + ii * 64 + ty * 4 + i;
            #pragma unroll
            for (int jj = 0; jj < 2; jj++) {
                const int c = bn * 128 + jj * 64 + tx * 4;
                const float4 bv = *reinterpret_cast<const float4*>(bias + c);
                float v0 = acc[ii * 4 + i][jj * 4 + 0] + bv.x;
                float v1 = acc[ii * 4 + i][jj * 4 + 1] + bv.y;
                float v2 = acc[ii * 4 + i][jj * 4 + 2] + bv.z;
                float v3 = acc[ii * 4 + i][jj * 4 + 3] + bv.w;
                if (EPI == 1) {  // exact GELU: 0.5 x (1+erf(x/sqrt2))
                    v0 = 0.5f * v0 * (1.0f + erff(v0 * 0.70710678118654752f));
                    v1 = 0.5f * v1 * (1.0f + erff(v1 * 0.70710678118654752f));
                    v2 = 0.5f * v2 * (1.0f + erff(v2 * 0.70710678118654752f));
                    v3 = 0.5f * v3 * (1.0f + erff(v3 * 0.70710678118654752f));
                } else if (EPI == 2) {
                    const float4 rv = *reinterpret_cast<const float4*>(res + (size_t)r * N + c);
                    v0 += rv.x; v1 += rv.y; v2 += rv.z; v3 += rv.w;
                }
                *reinterpret_cast<float4*>(C + (size_t)r * N + c) = make_float4(v0, v1, v2, v3);
            }
        }
    }
}

// ---------------------------------------------------------------------------
// Flash attention, fp32, non-causal, full softmax over L=2048.
// One block per (64-query tile, b*h). 256 threads = 16x16, 4x4 microtiles.
// Smem (floats): Qs[64][64] | KP (Ks stride 65 / Ps stride 64) | Kt[64][72] | Vs[64][64]
// ---------------------------------------------------------------------------
#define ATT_QS  0
#define ATT_KP  4096
#define ATT_KT  8256      /* 4096 + 64*65 */
#define ATT_VS  12864     /* 8256 + 64*72 */
#define ATT_FLOATS 16960  /* 12864 + 4096 */
#define ATT_SMEM_BYTES (ATT_FLOATS * 4)

__global__ __launch_bounds__(256)
void attn_kernel(const float* __restrict__ qkv, float* __restrict__ ctx)
{
    extern __shared__ float sm[];
    float* Qs = sm + ATT_QS;   // [64][64] q-row-major, pre-scaled
    float* KP = sm + ATT_KP;   // Ks: [kv][d] stride 65 ; later Ps: [q][kv] stride 64
    float* Kt = sm + ATT_KT;   // [d][kv] stride 72
    float* Vs = sm + ATT_VS;   // [kv][d] stride 64

    const int tid = threadIdx.x;
    const int ty  = tid >> 4, tx = tid & 15;
    const int b   = blockIdx.y >> 4, h = blockIdx.y & 15;
    const int q0  = blockIdx.x << 6;

    const float* qb = qkv + (size_t)b * L_SEQ * (3 * DM) + h * DH;
    const float* kb = qb + DM;
    const float* vb = qb + 2 * DM;

    const int lrow = tid >> 4;          // 0..15
    const int lc   = (tid & 15) << 2;   // 0..60

    // ---- load Q tile, pre-scaled by Dh^-0.5 = 0.125 ----
    #pragma unroll
    for (int p = 0; p < 4; p++) {
        const int r = p * 16 + lrow;
        float4 v = *reinterpret_cast<const float4*>(qb + (size_t)(q0 + r) * (3 * DM) + lc);
        v.x *= 0.125f; v.y *= 0.125f; v.z *= 0.125f; v.w *= 0.125f;
        *reinterpret_cast<float4*>(Qs + r * 64 + lc) = v;
    }

    float m[4], l[4], o[4][4];
    #pragma unroll
    for (int i = 0; i < 4; i++) {
        m[i] = -3.0e38f; l[i] = 0.f;
        #pragma unroll
        for (int j = 0; j < 4; j++) o[i][j] = 0.f;
    }

    for (int t = 0; t < L_SEQ / 64; t++) {
        const size_t base = (size_t)(t * 64) * (3 * DM);
        __syncthreads();   // prev-iter Ps/Vs consumed (also orders first-iter Qs)

        // ---- load K (staged, stride 65) and V (stride 64) ----
        #pragma unroll
        for (int p = 0; p < 4; p++) {
            const int r = p * 16 + lrow;
            const float4 k4 = *reinterpret_cast<const float4*>(kb + base + (size_t)r * (3 * DM) + lc);
            float* kd = KP + r * 65 + lc;
            kd[0] = k4.x; kd[1] = k4.y; kd[2] = k4.z; kd[3] = k4.w;
            const float4 v4 = *reinterpret_cast<const float4*>(vb + base + (size_t)r * (3 * DM) + lc);
            *reinterpret_cast<float4*>(Vs + r * 64 + lc) = v4;
        }
        __syncthreads();

        // ---- transpose Ks -> Kt (both directions bank-conflict-free) ----
        #pragma unroll
        for (int p = 0; p < 16; p++) {
            const int e  = p * 256 + tid;
            const int d  = e >> 6;
            const int kv = e & 63;
            Kt[d * 72 + kv] = KP[kv * 65 + d];
        }
        __syncthreads();

        // ---- S = Qs @ Kt : each thread 4 q-rows x 4 kv-cols ----
        float s[4][4];
        #pragma unroll
        for (int i = 0; i < 4; i++)
            #pragma unroll
            for (int j = 0; j < 4; j++) s[i][j] = 0.f;

        #pragma unroll 4
        for (int d4 = 0; d4 < 64; d4 += 4) {
            float qa[4][4], ka[4][4];
            #pragma unroll
            for (int i = 0; i < 4; i++) {
                const float4 q = *reinterpret_cast<const float4*>(Qs + (ty * 4 + i) * 64 + d4);
                qa[i][0] = q.x; qa[i][1] = q.y; qa[i][2] = q.z; qa[i][3] = q.w;
            }
            #pragma unroll
            for (int c = 0; c < 4; c++) {
                const float4 k = *reinterpret_cast<const float4*>(Kt + (d4 + c) * 72 + tx * 4);
                ka[c][0] = k.x; ka[c][1] = k.y; ka[c][2] = k.z; ka[c][3] = k.w;
            }
            #pragma unroll
            for (int c = 0; c < 4; c++)
                #pragma unroll
                for (int i = 0; i < 4; i++)
                    #pragma unroll
                    for (int j = 0; j < 4; j++)
                        s[i][j] = fmaf(qa[i][c], ka[c][j], s[i][j]);
        }

        // ---- online softmax (rows owned by 16 tx lanes; Ks no longer needed,
        //      so Ps may be written into the KP region) ----
        #pragma unroll
        for (int i = 0; i < 4; i++) {
            float mt = fmaxf(fmaxf(s[i][0], s[i][1]), fmaxf(s[i][2], s[i][3]));
            #pragma unroll
            for (int w = 1; w < 16; w <<= 1)
                mt = fmaxf(mt, __shfl_xor_sync(0xffffffffu, mt, w));
            const float mn   = fmaxf(m[i], mt);
            const float corr = __expf(m[i] - mn);
            m[i] = mn;
            float4 p;
            p.x = __expf(s[i][0] - mn);
            p.y = __expf(s[i][1] - mn);
            p.z = __expf(s[i][2] - mn);
            p.w = __expf(s[i][3] - mn);
            float rs = p.x + p.y + p.z + p.w;
            #pragma unroll
            for (int w = 1; w < 16; w <<= 1)
                rs += __shfl_xor_sync(0xffffffffu, rs, w);
            l[i] = l[i] * corr + rs;
            o[i][0] *= corr; o[i][1] *= corr; o[i][2] *= corr; o[i][3] *= corr;
            *reinterpret_cast<float4*>(KP + (ty * 4 + i) * 64 + tx * 4) = p;
        }
        __syncthreads();

        // ---- O += P @ V : thread 4 q-rows x 4 head-dims (tx*4..+3) ----
        #pragma unroll 4
        for (int kv = 0; kv < 64; kv += 4) {
            float pa_[4][4], va_[4][4];
            #pragma unroll
            for (int i = 0; i < 4; i++) {
                const float4 pp = *reinterpret_cast<const float4*>(KP + (ty * 4 + i) * 64 + kv);
                pa_[i][0] = pp.x; pa_[i][1] = pp.y; pa_[i][2] = pp.z; pa_[i][3] = pp.w;
            }
            #pragma unroll
            for (int c = 0; c < 4; c++) {
                const float4 vv = *reinterpret_cast<const float4*>(Vs + (kv + c) * 64 + tx * 4);
                va_[c][0] = vv.x; va_[c][1] = vv.y; va_[c][2] = vv.z; va_[c][3] = vv.w;
            }
            #pragma unroll
            for (int c = 0; c < 4; c++)
                #pragma unroll
                for (int i = 0; i < 4; i++)
                    #pragma unroll
                    for (int j = 0; j < 4; j++)
                        o[i][j] = fmaf(pa_[i][c], va_[c][j], o[i][j]);
        }
    }

    // ---- normalize + write ctx[b, q, h*64 + d] ----
    #pragma unroll
    for (int i = 0; i < 4; i++) {
        const float inv = 1.0f / l[i];
        float4 r;
        r.x = o[i][0] * inv; r.y = o[i][1] * inv;
        r.z = o[i][2] * inv; r.w = o[i][3] * inv;
        const size_t idx = (size_t)(b * L_SEQ + q0 + ty * 4 + i) * DM + h * DH + tx * 4;
        *reinterpret_cast<float4*>(ctx + idx) = r;
    }
}

// ---------------------------------------------------------------------------
// Launch: LN1 -> QKV -> attention -> out-proj(+res) -> LN2 -> FF1(GELU) -> FF2(+res)
// ---------------------------------------------------------------------------
extern "C" void kernel_launch(void* const* d_in, const int* in_sizes, int n_in,
                              void* d_out, int out_size)
{
    (void)in_sizes; (void)n_in; (void)out_size;
    const float* x     = (const float*)d_in[0];
    const float* qkv_w = (const float*)d_in[1];
    const float* qkv_b = (const float*)d_in[2];
    const float* out_w = (const float*)d_in[3];
    const float* out_b = (const float*)d_in[4];
    const float* ff1_w = (const float*)d_in[5];
    const float* ff1_b = (const float*)d_in[6];
    const float* ff2_w = (const float*)d_in[7];
    const float* ff2_b = (const float*)d_in[8];
    const float* ln1_g = (const float*)d_in[9];
    const float* ln1_b = (const float*)d_in[10];
    const float* ln2_g = (const float*)d_in[11];
    const float* ln2_b = (const float*)d_in[12];
    float* out = (float*)d_out;

    float *h, *qkv, *ctx, *ffh;
    cudaGetSymbolAddress((void**)&h,   g_h);
    cudaGetSymbolAddress((void**)&qkv, g_qkv);
    cudaGetSymbolAddress((void**)&ctx, g_ctx);
    cudaGetSymbolAddress((void**)&ffh, g_ffh);

    // attention needs > 48 KB dynamic smem (attribute set is not a stream op;
    // safe under graph capture, idempotent)
    cudaFuncSetAttribute(attn_kernel, cudaFuncAttributeMaxDynamicSharedMemorySize,
                         ATT_SMEM_BYTES);

    const dim3 blk(256);

    // 1) h = LN1(x)
    ln_kernel<<<NROWS, 256>>>(x, ln1_g, ln1_b, h);

    // 2) qkv = h @ qkv_w + qkv_b                      [8192, 3072]
    sgemm_kernel<0><<<dim3(3 * DM / 128, NROWS / 128), blk>>>(
        h, qkv_w, qkv_b, nullptr, qkv, NROWS, 3 * DM, DM);

    // 3) ctx = attention(q, k, v)                     [8192, 1024]
    attn_kernel<<<dim3(L_SEQ / 64, BATCH * NH), 256, ATT_SMEM_BYTES>>>(qkv, ctx);

    // 4) out = x + ctx @ out_w + out_b                [8192, 1024]
    sgemm_kernel<2><<<dim3(DM / 128, NROWS / 128), blk>>>(
        ctx, out_w, out_b, x, out, NROWS, DM, DM);

    // 5) h = LN2(out)
    ln_kernel<<<NROWS, 256>>>(out, ln2_g, ln2_b, h);

    // 6) ffh = GELU(h @ ff1_w + ff1_b)                [8192, 2048]
    sgemm_kernel<1><<<dim3(FFH / 128, NROWS / 128), blk>>>(
        h, ff1_w, ff1_b, nullptr, ffh, NROWS, FFH, DM);

    // 7) out = out + ffh @ ff2_w + ff2_b              [8192, 1024]
    sgemm_kernel<2><<<dim3(DM / 128, NROWS / 128), blk>>>(
        ffh, ff2_w, ff2_b, out, out, NROWS, DM, FFH);
}

// round 8
// speedup vs baseline: 1.4818x; 1.4818x over previous
#include <cuda_runtime.h>
#include <cuda_bf16.h>
#include <math.h>
#include <stdint.h>

// ---------------------------------------------------------------------------
// Problem constants
// ---------------------------------------------------------------------------
#define DM     1024
#define L_SEQ  2048
#define BATCH  4
#define NROWS  8192
#define NH     16
#define DH     64
#define FFH    2048

// ---------------------------------------------------------------------------
// Scratch (device globals; allocation-free per harness rules)
// ---------------------------------------------------------------------------
__device__ float         g_qkv[(size_t)NROWS * 3 * DM];
__device__ __nv_bfloat16 g_ah[(size_t)NROWS * FFH];
__device__ __nv_bfloat16 g_al[(size_t)NROWS * FFH];
__device__ __nv_bfloat16 g_bh[(size_t)NROWS * FFH];
__device__ __nv_bfloat16 g_bl[(size_t)NROWS * FFH];
__device__ __nv_bfloat16 g_w1h[(size_t)3 * DM * DM], g_w1l[(size_t)3 * DM * DM];
__device__ __nv_bfloat16 g_w2h[(size_t)DM * DM],     g_w2l[(size_t)DM * DM];
__device__ __nv_bfloat16 g_w3h[(size_t)FFH * DM],    g_w3l[(size_t)FFH * DM];
__device__ __nv_bfloat16 g_w4h[(size_t)DM * FFH],    g_w4l[(size_t)DM * FFH];

// ---------------------------------------------------------------------------
// PTX helpers (portable: cp.async / ldmatrix / mma.sync only)
// ---------------------------------------------------------------------------
__device__ __forceinline__ uint32_t smem_u32(const void* p) {
    uint32_t a;
    asm("{ .reg .u64 t; cvta.to.shared.u64 t, %1; cvt.u32.u64 %0, t; }" : "=r"(a) : "l"(p));
    return a;
}
__device__ __forceinline__ void cpa16(uint32_t dst, const void* src) {
    asm volatile("cp.async.cg.shared.global [%0], [%1], 16;" :: "r"(dst), "l"(src));
}
#define CP_COMMIT() asm volatile("cp.async.commit_group;" ::: "memory")
#define CP_WAIT(n)  asm volatile("cp.async.wait_group %0;" :: "n"(n) : "memory")

__device__ __forceinline__ void ldsm_x4(uint32_t addr, uint32_t& r0, uint32_t& r1,
                                        uint32_t& r2, uint32_t& r3) {
    asm volatile("ldmatrix.sync.aligned.m8n8.x4.shared.b16 {%0,%1,%2,%3}, [%4];"
                 : "=r"(r0), "=r"(r1), "=r"(r2), "=r"(r3) : "r"(addr));
}
__device__ __forceinline__ void mma16816(float* c, const uint32_t* a, const uint32_t* b) {
    asm volatile(
        "mma.sync.aligned.m16n8k16.row.col.f32.bf16.bf16.f32 "
        "{%0,%1,%2,%3}, {%4,%5,%6,%7}, {%8,%9}, {%0,%1,%2,%3};"
        : "+f"(c[0]), "+f"(c[1]), "+f"(c[2]), "+f"(c[3])
        : "r"(a[0]), "r"(a[1]), "r"(a[2]), "r"(a[3]), "r"(b[0]), "r"(b[1]));
}
__device__ __forceinline__ uint32_t sw128(uint32_t off) {
    return off ^ ((off >> 3) & 0x70);
}

// bf16 split: x = hi + lo
__device__ __forceinline__ void split2pack(float a, float b, uint32_t& hi, uint32_t& lo) {
    __nv_bfloat16 ha = __float2bfloat16(a), hb = __float2bfloat16(b);
    __nv_bfloat162 H; H.x = ha; H.y = hb;
    __nv_bfloat162 L;
    L.x = __float2bfloat16(a - __bfloat162float(ha));
    L.y = __float2bfloat16(b - __bfloat162float(hb));
    hi = *reinterpret_cast<uint32_t*>(&H);
    lo = *reinterpret_cast<uint32_t*>(&L);
}

// ---------------------------------------------------------------------------
// Weight transpose + split: W[K,N] fp32 -> Wh/Wl [N,K] bf16 (K-major)
// ---------------------------------------------------------------------------
__global__ void wsplit_kernel(const float* __restrict__ W,
                              __nv_bfloat16* __restrict__ Wh,
                              __nv_bfloat16* __restrict__ Wl, int K, int N)
{
    __shared__ float t[32][33];
    const int bx = blockIdx.x, by = blockIdx.y;
    const int tx = threadIdx.x, ty = threadIdx.y;
    #pragma unroll
    for (int j = 0; j < 4; j++)
        t[ty + j * 8][tx] = W[(size_t)(by * 32 + ty + j * 8) * N + bx * 32 + tx];
    __syncthreads();
    #pragma unroll
    for (int j = 0; j < 4; j++) {
        const float v = t[tx][ty + j * 8];
        const int n = bx * 32 + ty + j * 8, k = by * 32 + tx;
        const __nv_bfloat16 h = __float2bfloat16(v);
        Wh[(size_t)n * K + k] = h;
        Wl[(size_t)n * K + k] = __float2bfloat16(v - __bfloat162float(h));
    }
}

// ---------------------------------------------------------------------------
// LayerNorm -> hi/lo bf16
// ---------------------------------------------------------------------------
__global__ void ln_kernel(const float* __restrict__ x,
                          const float* __restrict__ gam,
                          const float* __restrict__ bet,
                          __nv_bfloat16* __restrict__ oh,
                          __nv_bfloat16* __restrict__ ol)
{
    const int row = blockIdx.x;
    const int t   = threadIdx.x;
    const float4 v = reinterpret_cast<const float4*>(x + (size_t)row * DM)[t];

    float s  = v.x + v.y + v.z + v.w;
    float ss = v.x*v.x + v.y*v.y + v.z*v.z + v.w*v.w;

    __shared__ float rs[8], rq[8];
    #pragma unroll
    for (int m = 16; m > 0; m >>= 1) {
        s  += __shfl_down_sync(0xffffffffu, s,  m);
        ss += __shfl_down_sync(0xffffffffu, ss, m);
    }
    if ((t & 31) == 0) { rs[t >> 5] = s; rq[t >> 5] = ss; }
    __syncthreads();
    if (t == 0) {
        float a = 0.f, b = 0.f;
        #pragma unroll
        for (int i = 0; i < 8; i++) { a += rs[i]; b += rq[i]; }
        rs[0] = a; rq[0] = b;
    }
    __syncthreads();

    const float mean = rs[0] * (1.0f / DM);
    const float var  = rq[0] * (1.0f / DM) - mean * mean;
    const float rstd = rsqrtf(var + 1e-5f);

    const float4 g4 = reinterpret_cast<const float4*>(gam)[t];
    const float4 b4 = reinterpret_cast<const float4*>(bet)[t];
    const float o0 = (v.x - mean) * rstd * g4.x + b4.x;
    const float o1 = (v.y - mean) * rstd * g4.y + b4.y;
    const float o2 = (v.z - mean) * rstd * g4.z + b4.z;
    const float o3 = (v.w - mean) * rstd * g4.w + b4.w;

    uint32_t h0, l0, h1, l1;
    split2pack(o0, o1, h0, l0);
    split2pack(o2, o3, h1, l1);
    const size_t idx = (size_t)row * DM + t * 4;
    *reinterpret_cast<uint2*>(oh + idx) = make_uint2(h0, h1);
    *reinterpret_cast<uint2*>(ol + idx) = make_uint2(l0, l1);
}

// ---------------------------------------------------------------------------
// mma.sync bf16x3 GEMM: C[M,N] = A[M,K] @ B_T[N,K]^T   (fp32 accuracy)
// 128x128 CTA tile, 8 warps (2x4), warp = 64x32 via 4x4 m16n8k16 frags.
// K chunks of 64, double-buffered cp.async (prefetch depth 1), SW128 smem.
// EPI: 0 = +bias -> fp32 ; 1 = +bias,GELU -> bf16 hi/lo ; 2 = +bias+res -> fp32
// ---------------------------------------------------------------------------
#define STG_AH 0
#define STG_AL 16384
#define STG_BH 32768
#define STG_BL 49152
#define STG_SZ 65536
#define TG_SMEM (2 * STG_SZ)   /* 128 KB */

__device__ __forceinline__ void fill_tile(uint32_t sdst, const __nv_bfloat16* g,
                                          int row0, int k0, int K, int tid)
{
    #pragma unroll
    for (int i = 0; i < 4; i++) {
        const int idx = i * 256 + tid;           // 1024 x 16B = 128x64 bf16
        const int r = idx >> 3, c = idx & 7;
        const uint32_t off = (uint32_t)(r * 128 + c * 16);
        const uint32_t so  = sdst + sw128(off);
        const char* src = (const char*)g + (((size_t)(row0 + r)) * K + (size_t)k0 + c * 8) * 2;
        cpa16(so, src);
    }
}

template<int EPI>
__global__ __launch_bounds__(256, 1)
void tgemm_kernel(const __nv_bfloat16* __restrict__ Ah, const __nv_bfloat16* __restrict__ Al,
                  const __nv_bfloat16* __restrict__ Bh, const __nv_bfloat16* __restrict__ Bl,
                  const float* __restrict__ bias, const float* __restrict__ res,
                  float* __restrict__ C,
                  __nv_bfloat16* __restrict__ Ch, __nv_bfloat16* __restrict__ Cl,
                  int N, int K)
{
    extern __shared__ char smem[];
    const uint32_t sb = smem_u32(smem);
    const int tid  = threadIdx.x;
    const int wid  = tid >> 5, lane = tid & 31;
    const int bm   = blockIdx.y, bn = blockIdx.x;
    const int wm   = (wid >> 2) * 64;   // warp row offset in tile
    const int wn   = (wid & 3) * 32;    // warp col offset in tile

    float acc[4][4][4];
    #pragma unroll
    for (int mt = 0; mt < 4; mt++)
        #pragma unroll
        for (int nt = 0; nt < 4; nt++)
            #pragma unroll
            for (int e = 0; e < 4; e++) acc[mt][nt][e] = 0.f;

    const int nch = K >> 6;

    // prefetch chunk 0
    fill_tile(sb + STG_AH, Ah, bm * 128, 0, K, tid);
    fill_tile(sb + STG_AL, Al, bm * 128, 0, K, tid);
    fill_tile(sb + STG_BH, Bh, bn * 128, 0, K, tid);
    fill_tile(sb + STG_BL, Bl, bn * 128, 0, K, tid);
    CP_COMMIT();

    for (int ch = 0; ch < nch; ++ch) {
        if (ch + 1 < nch) {
            const uint32_t nst = sb + ((ch + 1) & 1) * STG_SZ;
            const int k1 = (ch + 1) << 6;
            fill_tile(nst + STG_AH, Ah, bm * 128, k1, K, tid);
            fill_tile(nst + STG_AL, Al, bm * 128, k1, K, tid);
            fill_tile(nst + STG_BH, Bh, bn * 128, k1, K, tid);
            fill_tile(nst + STG_BL, Bl, bn * 128, k1, K, tid);
            CP_COMMIT();
            CP_WAIT(1);
        } else {
            CP_WAIT(0);
        }
        __syncthreads();

        const uint32_t st = sb + (ch & 1) * STG_SZ;
        #pragma unroll
        for (int ks = 0; ks < 4; ks++) {
            const uint32_t kb = (uint32_t)(ks * 32 + ((lane >> 4) << 4));
            uint32_t ah[4][4], al[4][4], bh[4][2], bl[4][2];
            #pragma unroll
            for (int mt = 0; mt < 4; mt++) {
                const uint32_t off = (uint32_t)((wm + mt * 16 + (lane & 15)) * 128) + kb;
                const uint32_t so  = sw128(off);
                ldsm_x4(st + STG_AH + so, ah[mt][0], ah[mt][1], ah[mt][2], ah[mt][3]);
                ldsm_x4(st + STG_AL + so, al[mt][0], al[mt][1], al[mt][2], al[mt][3]);
            }
            #pragma unroll
            for (int np = 0; np < 2; np++) {
                const uint32_t off = (uint32_t)((wn + np * 16 + (lane & 15)) * 128) + kb;
                const uint32_t so  = sw128(off);
                uint32_t r0, r1, r2, r3;
                ldsm_x4(st + STG_BH + so, r0, r1, r2, r3);
                bh[np * 2][0] = r0; bh[np * 2 + 1][0] = r1;
                bh[np * 2][1] = r2; bh[np * 2 + 1][1] = r3;
                ldsm_x4(st + STG_BL + so, r0, r1, r2, r3);
                bl[np * 2][0] = r0; bl[np * 2 + 1][0] = r1;
                bl[np * 2][1] = r2; bl[np * 2 + 1][1] = r3;
            }
            #pragma unroll
            for (int mt = 0; mt < 4; mt++)
                #pragma unroll
                for (int nt = 0; nt < 4; nt++) {
                    mma16816(acc[mt][nt], ah[mt], bh[nt]);
                    mma16816(acc[mt][nt], ah[mt], bl[nt]);
                    mma16816(acc[mt][nt], al[mt], bh[nt]);
                }
        }
        __syncthreads();
    }

    // ---- epilogue: fragment layout c0,c1 = row t/4, cols 2*(t%4)+{0,1};
    //      c2,c3 = row t/4+8 same cols ----
    const int rbase = bm * 128 + wm + (lane >> 2);
    const int cbase = bn * 128 + wn + (lane & 3) * 2;
    #pragma unroll
    for (int mt = 0; mt < 4; mt++) {
        #pragma unroll
        for (int half = 0; half < 2; half++) {
            const int r = rbase + mt * 16 + half * 8;
            const size_t rowoff = (size_t)r * N;
            #pragma unroll
            for (int nt = 0; nt < 4; nt++) {
                const int c = cbase + nt * 8;
                float v0 = acc[mt][nt][half * 2 + 0] + __ldg(bias + c);
                float v1 = acc[mt][nt][half * 2 + 1] + __ldg(bias + c + 1);
                if (EPI == 2) {
                    const float2 rv = *reinterpret_cast<const float2*>(res + rowoff + c);
                    v0 += rv.x; v1 += rv.y;
                }
                if (EPI == 1) {
                    v0 = 0.5f * v0 * (1.0f + erff(v0 * 0.70710678118654752f));
                    v1 = 0.5f * v1 * (1.0f + erff(v1 * 0.70710678118654752f));
                    uint32_t h, l;
                    split2pack(v0, v1, h, l);
                    *reinterpret_cast<uint32_t*>(Ch + rowoff + c) = h;
                    *reinterpret_cast<uint32_t*>(Cl + rowoff + c) = l;
                } else {
                    *reinterpret_cast<float2*>(C + rowoff + c) = make_float2(v0, v1);
                }
            }
        }
    }
}

// ---------------------------------------------------------------------------
// Flash attention, fp32; epilogue emits hi/lo bf16 ctx
// ---------------------------------------------------------------------------
#define ATT_QS  0
#define ATT_KP  4096
#define ATT_KT  8256
#define ATT_VS  12864
#define ATT_FLOATS 16960
#define ATT_SMEM_BYTES (ATT_FLOATS * 4)

__global__ __launch_bounds__(256)
void attn_kernel(const float* __restrict__ qkv,
                 __nv_bfloat16* __restrict__ ctx_h,
                 __nv_bfloat16* __restrict__ ctx_l)
{
    extern __shared__ float sm[];
    float* Qs = sm + ATT_QS;
    float* KP = sm + ATT_KP;
    float* Kt = sm + ATT_KT;
    float* Vs = sm + ATT_VS;

    const int tid = threadIdx.x;
    const int ty  = tid >> 4, tx = tid & 15;
    const int b   = blockIdx.y >> 4, h = blockIdx.y & 15;
    const int q0  = blockIdx.x << 6;

    const float* qb = qkv + (size_t)b * L_SEQ * (3 * DM) + h * DH;
    const float* kb = qb + DM;
    const float* vb = qb + 2 * DM;

    const int lrow = tid >> 4;
    const int lc   = (tid & 15) << 2;

    #pragma unroll
    for (int p = 0; p < 4; p++) {
        const int r = p * 16 + lrow;
        float4 v = *reinterpret_cast<const float4*>(qb + (size_t)(q0 + r) * (3 * DM) + lc);
        v.x *= 0.125f; v.y *= 0.125f; v.z *= 0.125f; v.w *= 0.125f;
        *reinterpret_cast<float4*>(Qs + r * 64 + lc) = v;
    }

    float m[4], l[4], o[4][4];
    #pragma unroll
    for (int i = 0; i < 4; i++) {
        m[i] = -3.0e38f; l[i] = 0.f;
        #pragma unroll
        for (int j = 0; j < 4; j++) o[i][j] = 0.f;
    }

    for (int t = 0; t < L_SEQ / 64; t++) {
        const size_t base = (size_t)(t * 64) * (3 * DM);
        __syncthreads();

        #pragma unroll
        for (int p = 0; p < 4; p++) {
            const int r = p * 16 + lrow;
            const float4 k4 = *reinterpret_cast<const float4*>(kb + base + (size_t)r * (3 * DM) + lc);
            float* kd = KP + r * 65 + lc;
            kd[0] = k4.x; kd[1] = k4.y; kd[2] = k4.z; kd[3] = k4.w;
            const float4 v4 = *reinterpret_cast<const float4*>(vb + base + (size_t)r * (3 * DM) + lc);
            *reinterpret_cast<float4*>(Vs + r * 64 + lc) = v4;
        }
        __syncthreads();

        #pragma unroll
        for (int p = 0; p < 16; p++) {
            const int e  = p * 256 + tid;
            const int d  = e >> 6;
            const int kv = e & 63;
            Kt[d * 72 + kv] = KP[kv * 65 + d];
        }
        __syncthreads();

        float s[4][4];
        #pragma unroll
        for (int i = 0; i < 4; i++)
            #pragma unroll
            for (int j = 0; j < 4; j++) s[i][j] = 0.f;

        #pragma unroll 4
        for (int d4 = 0; d4 < 64; d4 += 4) {
            float qa[4][4], ka[4][4];
            #pragma unroll
            for (int i = 0; i < 4; i++) {
                const float4 q = *reinterpret_cast<const float4*>(Qs + (ty * 4 + i) * 64 + d4);
                qa[i][0] = q.x; qa[i][1] = q.y; qa[i][2] = q.z; qa[i][3] = q.w;
            }
            #pragma unroll
            for (int c = 0; c < 4; c++) {
                const float4 k = *reinterpret_cast<const float4*>(Kt + (d4 + c) * 72 + tx * 4);
                ka[c][0] = k.x; ka[c][1] = k.y; ka[c][2] = k.z; ka[c][3] = k.w;
            }
            #pragma unroll
            for (int c = 0; c < 4; c++)
                #pragma unroll
                for (int i = 0; i < 4; i++)
                    #pragma unroll
                    for (int j = 0; j < 4; j++)
                        s[i][j] = fmaf(qa[i][c], ka[c][j], s[i][j]);
        }

        #pragma unroll
        for (int i = 0; i < 4; i++) {
            float mt = fmaxf(fmaxf(s[i][0], s[i][1]), fmaxf(s[i][2], s[i][3]));
            #pragma unroll
            for (int w = 1; w < 16; w <<= 1)
                mt = fmaxf(mt, __shfl_xor_sync(0xffffffffu, mt, w));
            const float mn   = fmaxf(m[i], mt);
            const float corr = __expf(m[i] - mn);
            m[i] = mn;
            float4 p;
            p.x = __expf(s[i][0] - mn);
            p.y = __expf(s[i][1] - mn);
            p.z = __expf(s[i][2] - mn);
            p.w = __expf(s[i][3] - mn);
            float rs = p.x + p.y + p.z + p.w;
            #pragma unroll
            for (int w = 1; w < 16; w <<= 1)
                rs += __shfl_xor_sync(0xffffffffu, rs, w);
            l[i] = l[i] * corr + rs;
            o[i][0] *= corr; o[i][1] *= corr; o[i][2] *= corr; o[i][3] *= corr;
            *reinterpret_cast<float4*>(KP + (ty * 4 + i) * 64 + tx * 4) = p;
        }
        __syncthreads();

        #pragma unroll 4
        for (int kv = 0; kv < 64; kv += 4) {
            float pa_[4][4], va_[4][4];
            #pragma unroll
            for (int i = 0; i < 4; i++) {
                const float4 pp = *reinterpret_cast<const float4*>(KP + (ty * 4 + i) * 64 + kv);
                pa_[i][0] = pp.x; pa_[i][1] = pp.y; pa_[i][2] = pp.z; pa_[i][3] = pp.w;
            }
            #pragma unroll
            for (int c = 0; c < 4; c++) {
                const float4 vv = *reinterpret_cast<const float4*>(Vs + (kv + c) * 64 + tx * 4);
                va_[c][0] = vv.x; va_[c][1] = vv.y; va_[c][2] = vv.z; va_[c][3] = vv.w;
            }
            #pragma unroll
            for (int c = 0; c < 4; c++)
                #pragma unroll
                for (int i = 0; i < 4; i++)
                    #pragma unroll
                    for (int j = 0; j < 4; j++)
                        o[i][j] = fmaf(pa_[i][c], va_[c][j], o[i][j]);
        }
    }

    #pragma unroll
    for (int i = 0; i < 4; i++) {
        const float inv = 1.0f / l[i];
        const float r0 = o[i][0] * inv, r1 = o[i][1] * inv;
        const float r2 = o[i][2] * inv, r3 = o[i][3] * inv;
        uint32_t h0, l0_, h1, l1;
        split2pack(r0, r1, h0, l0_);
        split2pack(r2, r3, h1, l1);
        const size_t idx = (size_t)(b * L_SEQ + q0 + ty * 4 + i) * DM + h * DH + tx * 4;
        *reinterpret_cast<uint2*>(ctx_h + idx) = make_uint2(h0, h1);
        *reinterpret_cast<uint2*>(ctx_l + idx) = make_uint2(l0_, l1);
    }
}

// ---------------------------------------------------------------------------
// Launch
// ---------------------------------------------------------------------------
extern "C" void kernel_launch(void* const* d_in, const int* in_sizes, int n_in,
                              void* d_out, int out_size)
{
    (void)in_sizes; (void)n_in; (void)out_size;
    const float* x     = (const float*)d_in[0];
    const float* qkv_w = (const float*)d_in[1];
    const float* qkv_b = (const float*)d_in[2];
    const float* out_w = (const float*)d_in[3];
    const float* out_b = (const float*)d_in[4];
    const float* ff1_w = (const float*)d_in[5];
    const float* ff1_b = (const float*)d_in[6];
    const float* ff2_w = (const float*)d_in[7];
    const float* ff2_b = (const float*)d_in[8];
    const float* ln1_g = (const float*)d_in[9];
    const float* ln1_b = (const float*)d_in[10];
    const float* ln2_g = (const float*)d_in[11];
    const float* ln2_b = (const float*)d_in[12];
    float* out = (float*)d_out;

    float* qkv;
    __nv_bfloat16 *ah, *al, *bh, *bl;
    __nv_bfloat16 *w1h, *w1l, *w2h, *w2l, *w3h, *w3l, *w4h, *w4l;
    cudaGetSymbolAddress((void**)&qkv, g_qkv);
    cudaGetSymbolAddress((void**)&ah, g_ah);  cudaGetSymbolAddress((void**)&al, g_al);
    cudaGetSymbolAddress((void**)&bh, g_bh);  cudaGetSymbolAddress((void**)&bl, g_bl);
    cudaGetSymbolAddress((void**)&w1h, g_w1h); cudaGetSymbolAddress((void**)&w1l, g_w1l);
    cudaGetSymbolAddress((void**)&w2h, g_w2h); cudaGetSymbolAddress((void**)&w2l, g_w2l);
    cudaGetSymbolAddress((void**)&w3h, g_w3h); cudaGetSymbolAddress((void**)&w3l, g_w3l);
    cudaGetSymbolAddress((void**)&w4h, g_w4h); cudaGetSymbolAddress((void**)&w4l, g_w4l);

    cudaFuncSetAttribute(attn_kernel, cudaFuncAttributeMaxDynamicSharedMemorySize,
                         ATT_SMEM_BYTES);
    cudaFuncSetAttribute(tgemm_kernel<0>, cudaFuncAttributeMaxDynamicSharedMemorySize, TG_SMEM);
    cudaFuncSetAttribute(tgemm_kernel<1>, cudaFuncAttributeMaxDynamicSharedMemorySize, TG_SMEM);
    cudaFuncSetAttribute(tgemm_kernel<2>, cudaFuncAttributeMaxDynamicSharedMemorySize, TG_SMEM);

    const dim3 tb(32, 8);

    // 0) weight transpose + bf16 split
    wsplit_kernel<<<dim3(3 * DM / 32, DM / 32),  tb>>>(qkv_w, w1h, w1l, DM,  3 * DM);
    wsplit_kernel<<<dim3(DM / 32,     DM / 32),  tb>>>(out_w, w2h, w2l, DM,  DM);
    wsplit_kernel<<<dim3(FFH / 32,    DM / 32),  tb>>>(ff1_w, w3h, w3l, DM,  FFH);
    wsplit_kernel<<<dim3(DM / 32,     FFH / 32), tb>>>(ff2_w, w4h, w4l, FFH, DM);

    // 1) bufA = LN1(x)
    ln_kernel<<<NROWS, 256>>>(x, ln1_g, ln1_b, ah, al);

    // 2) qkv = bufA @ qkv_w + qkv_b                   [8192, 3072] fp32
    tgemm_kernel<0><<<dim3(3 * DM / 128, NROWS / 128), 256, TG_SMEM>>>(
        ah, al, w1h, w1l, qkv_b, nullptr, qkv, nullptr, nullptr, 3 * DM, DM);

    // 3) bufB = attention(qkv)
    attn_kernel<<<dim3(L_SEQ / 64, BATCH * NH), 256, ATT_SMEM_BYTES>>>(qkv, bh, bl);

    // 4) out = x + bufB @ out_w + out_b               [8192, 1024] fp32
    tgemm_kernel<2><<<dim3(DM / 128, NROWS / 128), 256, TG_SMEM>>>(
        bh, bl, w2h, w2l, out_b, x, out, nullptr, nullptr, DM, DM);

    // 5) bufA = LN2(out)
    ln_kernel<<<NROWS, 256>>>(out, ln2_g, ln2_b, ah, al);

    // 6) bufB = GELU(bufA @ ff1_w + ff1_b)            [8192, 2048] hi/lo
    tgemm_kernel<1><<<dim3(FFH / 128, NROWS / 128), 256, TG_SMEM>>>(
        ah, al, w3h, w3l, ff1_b, nullptr, nullptr, bh, bl, FFH, DM);

    // 7) out = out + bufB @ ff2_w + ff2_b             [8192, 1024] fp32
    tgemm_kernel<2><<<dim3(DM / 128, NROWS / 128), 256, TG_SMEM>>>(
        bh, bl, w4h, w4l, ff2_b, out, out, nullptr, nullptr, DM, FFH);
}

// round 9
// speedup vs baseline: 1.6103x; 1.0867x over previous
#include <cuda_runtime.h>
#include <cuda_bf16.h>
#include <math.h>
#include <stdint.h>

// ---------------------------------------------------------------------------
// Problem constants
// ---------------------------------------------------------------------------
#define DM     1024
#define L_SEQ  2048
#define BATCH  4
#define NROWS  8192
#define NH     16
#define DH     64
#define FFH    2048

// ---------------------------------------------------------------------------
// Scratch (device globals; allocation-free per harness rules)
// ---------------------------------------------------------------------------
__device__ __nv_bfloat16 g_qh[(size_t)NROWS * 3 * DM];   // qkv hi (q pre-scaled)
__device__ __nv_bfloat16 g_ql[(size_t)NROWS * 3 * DM];   // qkv lo
__device__ __nv_bfloat16 g_ah[(size_t)NROWS * FFH];
__device__ __nv_bfloat16 g_al[(size_t)NROWS * FFH];
__device__ __nv_bfloat16 g_bh[(size_t)NROWS * FFH];
__device__ __nv_bfloat16 g_bl[(size_t)NROWS * FFH];
__device__ __nv_bfloat16 g_w1h[(size_t)3 * DM * DM], g_w1l[(size_t)3 * DM * DM];
__device__ __nv_bfloat16 g_w2h[(size_t)DM * DM],     g_w2l[(size_t)DM * DM];
__device__ __nv_bfloat16 g_w3h[(size_t)FFH * DM],    g_w3l[(size_t)FFH * DM];
__device__ __nv_bfloat16 g_w4h[(size_t)DM * FFH],    g_w4l[(size_t)DM * FFH];

// ---------------------------------------------------------------------------
// PTX helpers (portable: cp.async / ldmatrix / mma.sync only)
// ---------------------------------------------------------------------------
__device__ __forceinline__ uint32_t smem_u32(const void* p) {
    uint32_t a;
    asm("{ .reg .u64 t; cvta.to.shared.u64 t, %1; cvt.u32.u64 %0, t; }" : "=r"(a) : "l"(p));
    return a;
}
__device__ __forceinline__ void cpa16(uint32_t dst, const void* src) {
    asm volatile("cp.async.cg.shared.global [%0], [%1], 16;" :: "r"(dst), "l"(src));
}
#define CP_COMMIT() asm volatile("cp.async.commit_group;" ::: "memory")
#define CP_WAIT(n)  asm volatile("cp.async.wait_group %0;" :: "n"(n) : "memory")

__device__ __forceinline__ void ldsm_x4(uint32_t addr, uint32_t& r0, uint32_t& r1,
                                        uint32_t& r2, uint32_t& r3) {
    asm volatile("ldmatrix.sync.aligned.m8n8.x4.shared.b16 {%0,%1,%2,%3}, [%4];"
                 : "=r"(r0), "=r"(r1), "=r"(r2), "=r"(r3) : "r"(addr));
}
__device__ __forceinline__ void ldsm_x4_t(uint32_t addr, uint32_t& r0, uint32_t& r1,
                                          uint32_t& r2, uint32_t& r3) {
    asm volatile("ldmatrix.sync.aligned.m8n8.x4.trans.shared.b16 {%0,%1,%2,%3}, [%4];"
                 : "=r"(r0), "=r"(r1), "=r"(r2), "=r"(r3) : "r"(addr));
}
__device__ __forceinline__ void mma16816(float* c, const uint32_t* a, const uint32_t* b) {
    asm volatile(
        "mma.sync.aligned.m16n8k16.row.col.f32.bf16.bf16.f32 "
        "{%0,%1,%2,%3}, {%4,%5,%6,%7}, {%8,%9}, {%0,%1,%2,%3};"
        : "+f"(c[0]), "+f"(c[1]), "+f"(c[2]), "+f"(c[3])
        : "r"(a[0]), "r"(a[1]), "r"(a[2]), "r"(a[3]), "r"(b[0]), "r"(b[1]));
}
__device__ __forceinline__ uint32_t sw128(uint32_t off) {
    return off ^ ((off >> 3) & 0x70);
}

// bf16 split: x = hi + lo
__device__ __forceinline__ void split2pack(float a, float b, uint32_t& hi, uint32_t& lo) {
    __nv_bfloat16 ha = __float2bfloat16(a), hb = __float2bfloat16(b);
    __nv_bfloat162 H; H.x = ha; H.y = hb;
    __nv_bfloat162 L;
    L.x = __float2bfloat16(a - __bfloat162float(ha));
    L.y = __float2bfloat16(b - __bfloat162float(hb));
    hi = *reinterpret_cast<uint32_t*>(&H);
    lo = *reinterpret_cast<uint32_t*>(&L);
}

// ---------------------------------------------------------------------------
// Weight transpose + split: W[K,N] fp32 -> Wh/Wl [N,K] bf16 (K-major)
// ---------------------------------------------------------------------------
__global__ void wsplit_kernel(const float* __restrict__ W,
                              __nv_bfloat16* __restrict__ Wh,
                              __nv_bfloat16* __restrict__ Wl, int K, int N)
{
    __shared__ float t[32][33];
    const int bx = blockIdx.x, by = blockIdx.y;
    const int tx = threadIdx.x, ty = threadIdx.y;
    #pragma unroll
    for (int j = 0; j < 4; j++)
        t[ty + j * 8][tx] = W[(size_t)(by * 32 + ty + j * 8) * N + bx * 32 + tx];
    __syncthreads();
    #pragma unroll
    for (int j = 0; j < 4; j++) {
        const float v = t[tx][ty + j * 8];
        const int n = bx * 32 + ty + j * 8, k = by * 32 + tx;
        const __nv_bfloat16 h = __float2bfloat16(v);
        Wh[(size_t)n * K + k] = h;
        Wl[(size_t)n * K + k] = __float2bfloat16(v - __bfloat162float(h));
    }
}

// ---------------------------------------------------------------------------
// LayerNorm -> hi/lo bf16
// ---------------------------------------------------------------------------
__global__ void ln_kernel(const float* __restrict__ x,
                          const float* __restrict__ gam,
                          const float* __restrict__ bet,
                          __nv_bfloat16* __restrict__ oh,
                          __nv_bfloat16* __restrict__ ol)
{
    const int row = blockIdx.x;
    const int t   = threadIdx.x;
    const float4 v = reinterpret_cast<const float4*>(x + (size_t)row * DM)[t];

    float s  = v.x + v.y + v.z + v.w;
    float ss = v.x*v.x + v.y*v.y + v.z*v.z + v.w*v.w;

    __shared__ float rs[8], rq[8];
    #pragma unroll
    for (int m = 16; m > 0; m >>= 1) {
        s  += __shfl_down_sync(0xffffffffu, s,  m);
        ss += __shfl_down_sync(0xffffffffu, ss, m);
    }
    if ((t & 31) == 0) { rs[t >> 5] = s; rq[t >> 5] = ss; }
    __syncthreads();
    if (t == 0) {
        float a = 0.f, b = 0.f;
        #pragma unroll
        for (int i = 0; i < 8; i++) { a += rs[i]; b += rq[i]; }
        rs[0] = a; rq[0] = b;
    }
    __syncthreads();

    const float mean = rs[0] * (1.0f / DM);
    const float var  = rq[0] * (1.0f / DM) - mean * mean;
    const float rstd = rsqrtf(var + 1e-5f);

    const float4 g4 = reinterpret_cast<const float4*>(gam)[t];
    const float4 b4 = reinterpret_cast<const float4*>(bet)[t];
    const float o0 = (v.x - mean) * rstd * g4.x + b4.x;
    const float o1 = (v.y - mean) * rstd * g4.y + b4.y;
    const float o2 = (v.z - mean) * rstd * g4.z + b4.z;
    const float o3 = (v.w - mean) * rstd * g4.w + b4.w;

    uint32_t h0, l0, h1, l1;
    split2pack(o0, o1, h0, l0);
    split2pack(o2, o3, h1, l1);
    const size_t idx = (size_t)row * DM + t * 4;
    *reinterpret_cast<uint2*>(oh + idx) = make_uint2(h0, h1);
    *reinterpret_cast<uint2*>(ol + idx) = make_uint2(l0, l1);
}

// ---------------------------------------------------------------------------
// Shared tile loader: 128 rows x 64 bf16 cols, row stride 'ldg' elems, SW128.
// ---------------------------------------------------------------------------
__device__ __forceinline__ void fill_tile(uint32_t sdst, const __nv_bfloat16* g,
                                          int row0, int k0, int ldg, int tid)
{
    #pragma unroll
    for (int i = 0; i < 4; i++) {
        const int idx = i * 256 + tid;           // 1024 x 16B = 128x64 bf16
        const int r = idx >> 3, c = idx & 7;
        const uint32_t off = (uint32_t)(r * 128 + c * 16);
        const uint32_t so  = sdst + sw128(off);
        const char* src = (const char*)g + (((size_t)(row0 + r)) * ldg + (size_t)k0 + c * 8) * 2;
        cpa16(so, src);
    }
}

// ---------------------------------------------------------------------------
// mma.sync bf16x3 GEMM: C[M,N] = A[M,K] @ B_T[N,K]^T   (fp32 accuracy)
// EPI: 1 = +bias,GELU -> bf16 hi/lo ; 2 = +bias+res -> fp32 ;
//      3 = +bias, scale q-cols by 0.125 -> bf16 hi/lo (for qkv)
// ---------------------------------------------------------------------------
#define STG_AH 0
#define STG_AL 16384
#define STG_BH 32768
#define STG_BL 49152
#define STG_SZ 65536
#define TG_SMEM (2 * STG_SZ)   /* 128 KB */

template<int EPI>
__global__ __launch_bounds__(256, 1)
void tgemm_kernel(const __nv_bfloat16* __restrict__ Ah, const __nv_bfloat16* __restrict__ Al,
                  const __nv_bfloat16* __restrict__ Bh, const __nv_bfloat16* __restrict__ Bl,
                  const float* __restrict__ bias, const float* __restrict__ res,
                  float* __restrict__ C,
                  __nv_bfloat16* __restrict__ Ch, __nv_bfloat16* __restrict__ Cl,
                  int N, int K)
{
    extern __shared__ char smem[];
    const uint32_t sb = smem_u32(smem);
    const int tid  = threadIdx.x;
    const int wid  = tid >> 5, lane = tid & 31;
    const int bm   = blockIdx.y, bn = blockIdx.x;
    const int wm   = (wid >> 2) * 64;
    const int wn   = (wid & 3) * 32;

    float acc[4][4][4];
    #pragma unroll
    for (int mt = 0; mt < 4; mt++)
        #pragma unroll
        for (int nt = 0; nt < 4; nt++)
            #pragma unroll
            for (int e = 0; e < 4; e++) acc[mt][nt][e] = 0.f;

    const int nch = K >> 6;

    fill_tile(sb + STG_AH, Ah, bm * 128, 0, K, tid);
    fill_tile(sb + STG_AL, Al, bm * 128, 0, K, tid);
    fill_tile(sb + STG_BH, Bh, bn * 128, 0, K, tid);
    fill_tile(sb + STG_BL, Bl, bn * 128, 0, K, tid);
    CP_COMMIT();

    for (int ch = 0; ch < nch; ++ch) {
        if (ch + 1 < nch) {
            const uint32_t nst = sb + ((ch + 1) & 1) * STG_SZ;
            const int k1 = (ch + 1) << 6;
            fill_tile(nst + STG_AH, Ah, bm * 128, k1, K, tid);
            fill_tile(nst + STG_AL, Al, bm * 128, k1, K, tid);
            fill_tile(nst + STG_BH, Bh, bn * 128, k1, K, tid);
            fill_tile(nst + STG_BL, Bl, bn * 128, k1, K, tid);
            CP_COMMIT();
            CP_WAIT(1);
        } else {
            CP_WAIT(0);
        }
        __syncthreads();

        const uint32_t st = sb + (ch & 1) * STG_SZ;
        #pragma unroll
        for (int ks = 0; ks < 4; ks++) {
            const uint32_t kb = (uint32_t)(ks * 32 + ((lane >> 4) << 4));
            uint32_t ah[4][4], al[4][4], bh[4][2], bl[4][2];
            #pragma unroll
            for (int mt = 0; mt < 4; mt++) {
                const uint32_t off = (uint32_t)((wm + mt * 16 + (lane & 15)) * 128) + kb;
                const uint32_t so  = sw128(off);
                ldsm_x4(st + STG_AH + so, ah[mt][0], ah[mt][1], ah[mt][2], ah[mt][3]);
                ldsm_x4(st + STG_AL + so, al[mt][0], al[mt][1], al[mt][2], al[mt][3]);
            }
            #pragma unroll
            for (int np = 0; np < 2; np++) {
                const uint32_t off = (uint32_t)((wn + np * 16 + (lane & 15)) * 128) + kb;
                const uint32_t so  = sw128(off);
                uint32_t r0, r1, r2, r3;
                ldsm_x4(st + STG_BH + so, r0, r1, r2, r3);
                bh[np * 2][0] = r0; bh[np * 2 + 1][0] = r1;
                bh[np * 2][1] = r2; bh[np * 2 + 1][1] = r3;
                ldsm_x4(st + STG_BL + so, r0, r1, r2, r3);
                bl[np * 2][0] = r0; bl[np * 2 + 1][0] = r1;
                bl[np * 2][1] = r2; bl[np * 2 + 1][1] = r3;
            }
            #pragma unroll
            for (int mt = 0; mt < 4; mt++)
                #pragma unroll
                for (int nt = 0; nt < 4; nt++) {
                    mma16816(acc[mt][nt], ah[mt], bh[nt]);
                    mma16816(acc[mt][nt], ah[mt], bl[nt]);
                    mma16816(acc[mt][nt], al[mt], bh[nt]);
                }
        }
        __syncthreads();
    }

    const int rbase = bm * 128 + wm + (lane >> 2);
    const int cbase = bn * 128 + wn + (lane & 3) * 2;
    #pragma unroll
    for (int mt = 0; mt < 4; mt++) {
        #pragma unroll
        for (int half = 0; half < 2; half++) {
            const int r = rbase + mt * 16 + half * 8;
            const size_t rowoff = (size_t)r * N;
            #pragma unroll
            for (int nt = 0; nt < 4; nt++) {
                const int c = cbase + nt * 8;
                float v0 = acc[mt][nt][half * 2 + 0] + __ldg(bias + c);
                float v1 = acc[mt][nt][half * 2 + 1] + __ldg(bias + c + 1);
                if (EPI == 2) {
                    const float2 rv = *reinterpret_cast<const float2*>(res + rowoff + c);
                    v0 += rv.x; v1 += rv.y;
                    *reinterpret_cast<float2*>(C + rowoff + c) = make_float2(v0, v1);
                } else if (EPI == 1) {
                    v0 = 0.5f * v0 * (1.0f + erff(v0 * 0.70710678118654752f));
                    v1 = 0.5f * v1 * (1.0f + erff(v1 * 0.70710678118654752f));
                    uint32_t h, l;
                    split2pack(v0, v1, h, l);
                    *reinterpret_cast<uint32_t*>(Ch + rowoff + c) = h;
                    *reinterpret_cast<uint32_t*>(Cl + rowoff + c) = l;
                } else {  // EPI == 3
                    const float sc = (c < DM) ? 0.125f : 1.0f;  // q-scale, exact
                    v0 *= sc; v1 *= sc;
                    uint32_t h, l;
                    split2pack(v0, v1, h, l);
                    *reinterpret_cast<uint32_t*>(Ch + rowoff + c) = h;
                    *reinterpret_cast<uint32_t*>(Cl + rowoff + c) = l;
                }
            }
        }
    }
}

// ---------------------------------------------------------------------------
// Tensor-core flash attention, bf16x3 split, fp32 accumulate.
// CTA = 128 q-rows x (b,h); 8 warps x 16 rows. KV tiles of 128, double-buffered.
// ---------------------------------------------------------------------------
#define AT_QH   0
#define AT_QL   16384
#define AT_STG  32768
#define AT_KH   0
#define AT_KL   16384
#define AT_VH   32768
#define AT_VL   49152
#define AT_STG_SZ 65536
#define AT_SMEM (AT_STG + 2 * AT_STG_SZ)   /* 160 KB */

__global__ __launch_bounds__(256, 1)
void attn_kernel(const __nv_bfloat16* __restrict__ qh,
                 const __nv_bfloat16* __restrict__ ql,
                 __nv_bfloat16* __restrict__ ctx_h,
                 __nv_bfloat16* __restrict__ ctx_l)
{
    extern __shared__ char smem[];
    const uint32_t sb = smem_u32(smem);
    const int tid  = threadIdx.x;
    const int wid  = tid >> 5, lane = tid & 31;
    const int b    = blockIdx.y >> 4, h = blockIdx.y & 15;
    const int q0   = blockIdx.x * 128;
    const int wm   = wid * 16;

    const int qcol = h * DH;
    const int kcol = DM + h * DH;
    const int vcol = 2 * DM + h * DH;
    const int rowQ = b * L_SEQ + q0;
    const int rowB = b * L_SEQ;

    // stage Q + KV tile 0 (one cp.async group)
    fill_tile(sb + AT_QH, qh, rowQ, qcol, 3 * DM, tid);
    fill_tile(sb + AT_QL, ql, rowQ, qcol, 3 * DM, tid);
    fill_tile(sb + AT_STG + AT_KH, qh, rowB, kcol, 3 * DM, tid);
    fill_tile(sb + AT_STG + AT_KL, ql, rowB, kcol, 3 * DM, tid);
    fill_tile(sb + AT_STG + AT_VH, qh, rowB, vcol, 3 * DM, tid);
    fill_tile(sb + AT_STG + AT_VL, ql, rowB, vcol, 3 * DM, tid);
    CP_COMMIT();

    uint32_t qfh[4][4], qfl[4][4];
    float m0 = -3.0e38f, m1 = -3.0e38f, l0 = 0.f, l1 = 0.f;
    float of[8][4];
    #pragma unroll
    for (int j = 0; j < 8; j++)
        #pragma unroll
        for (int e = 0; e < 4; e++) of[j][e] = 0.f;

    for (int t = 0; t < L_SEQ / 128; t++) {
        if (t + 1 < L_SEQ / 128) {
            const uint32_t nst = sb + AT_STG + ((t + 1) & 1) * AT_STG_SZ;
            const int rk = rowB + (t + 1) * 128;
            fill_tile(nst + AT_KH, qh, rk, kcol, 3 * DM, tid);
            fill_tile(nst + AT_KL, ql, rk, kcol, 3 * DM, tid);
            fill_tile(nst + AT_VH, qh, rk, vcol, 3 * DM, tid);
            fill_tile(nst + AT_VL, ql, rk, vcol, 3 * DM, tid);
            CP_COMMIT();
            CP_WAIT(1);
        } else {
            CP_WAIT(0);
        }
        __syncthreads();

        if (t == 0) {  // Q fragments (once)
            #pragma unroll
            for (int kb = 0; kb < 4; kb++) {
                const uint32_t off = (uint32_t)((wm + (lane & 15)) * 128 + kb * 32
                                               + ((lane >> 4) << 4));
                const uint32_t so = sw128(off);
                ldsm_x4(sb + AT_QH + so, qfh[kb][0], qfh[kb][1], qfh[kb][2], qfh[kb][3]);
                ldsm_x4(sb + AT_QL + so, qfl[kb][0], qfl[kb][1], qfl[kb][2], qfl[kb][3]);
            }
        }

        const uint32_t st = sb + AT_STG + (t & 1) * AT_STG_SZ;

        // ---- S = Q @ K^T (3-term), sf[16] n-frags of 8 kv cols ----
        float sf[16][4];
        #pragma unroll
        for (int j = 0; j < 16; j++)
            #pragma unroll
            for (int e = 0; e < 4; e++) sf[j][e] = 0.f;

        #pragma unroll
        for (int kb = 0; kb < 4; kb++)
            #pragma unroll
            for (int np = 0; np < 8; np++) {
                const uint32_t off = (uint32_t)((np * 16 + (lane & 15)) * 128 + kb * 32
                                               + ((lane >> 4) << 4));
                const uint32_t so = sw128(off);
                uint32_t r0, r1, r2, r3;
                ldsm_x4(st + AT_KH + so, r0, r1, r2, r3);
                uint32_t kh0[2] = {r0, r2}, kh1[2] = {r1, r3};
                ldsm_x4(st + AT_KL + so, r0, r1, r2, r3);
                uint32_t kl0[2] = {r0, r2}, kl1[2] = {r1, r3};
                mma16816(sf[2 * np],     qfh[kb], kh0);
                mma16816(sf[2 * np],     qfh[kb], kl0);
                mma16816(sf[2 * np],     qfl[kb], kh0);
                mma16816(sf[2 * np + 1], qfh[kb], kh1);
                mma16816(sf[2 * np + 1], qfh[kb], kl1);
                mma16816(sf[2 * np + 1], qfl[kb], kh1);
            }

        // ---- online softmax on fragments (rows r = lane>>2 and r+8) ----
        float mt0 = -3.0e38f, mt1 = -3.0e38f;
        #pragma unroll
        for (int j = 0; j < 16; j++) {
            mt0 = fmaxf(mt0, fmaxf(sf[j][0], sf[j][1]));
            mt1 = fmaxf(mt1, fmaxf(sf[j][2], sf[j][3]));
        }
        mt0 = fmaxf(mt0, __shfl_xor_sync(0xffffffffu, mt0, 1));
        mt0 = fmaxf(mt0, __shfl_xor_sync(0xffffffffu, mt0, 2));
        mt1 = fmaxf(mt1, __shfl_xor_sync(0xffffffffu, mt1, 1));
        mt1 = fmaxf(mt1, __shfl_xor_sync(0xffffffffu, mt1, 2));

        const float mn0 = fmaxf(m0, mt0), mn1 = fmaxf(m1, mt1);
        const float cr0 = __expf(m0 - mn0), cr1 = __expf(m1 - mn1);
        m0 = mn0; m1 = mn1;

        float rs0 = 0.f, rs1 = 0.f;
        #pragma unroll
        for (int j = 0; j < 16; j++) {
            sf[j][0] = __expf(sf[j][0] - mn0);
            sf[j][1] = __expf(sf[j][1] - mn0);
            sf[j][2] = __expf(sf[j][2] - mn1);
            sf[j][3] = __expf(sf[j][3] - mn1);
            rs0 += sf[j][0] + sf[j][1];
            rs1 += sf[j][2] + sf[j][3];
        }
        rs0 += __shfl_xor_sync(0xffffffffu, rs0, 1);
        rs0 += __shfl_xor_sync(0xffffffffu, rs0, 2);
        rs1 += __shfl_xor_sync(0xffffffffu, rs1, 1);
        rs1 += __shfl_xor_sync(0xffffffffu, rs1, 2);
        l0 = l0 * cr0 + rs0;
        l1 = l1 * cr1 + rs1;
        #pragma unroll
        for (int j = 0; j < 8; j++) {
            of[j][0] *= cr0; of[j][1] *= cr0;
            of[j][2] *= cr1; of[j][3] *= cr1;
        }

        // ---- O += P @ V (3-term), V^T frags via ldmatrix.trans ----
        #pragma unroll
        for (int kb2 = 0; kb2 < 8; kb2++) {
            uint32_t ph[4], pl[4];
            split2pack(sf[2 * kb2][0],     sf[2 * kb2][1],     ph[0], pl[0]);
            split2pack(sf[2 * kb2][2],     sf[2 * kb2][3],     ph[1], pl[1]);
            split2pack(sf[2 * kb2 + 1][0], sf[2 * kb2 + 1][1], ph[2], pl[2]);
            split2pack(sf[2 * kb2 + 1][2], sf[2 * kb2 + 1][3], ph[3], pl[3]);
            #pragma unroll
            for (int dp = 0; dp < 4; dp++) {
                const uint32_t off = (uint32_t)((kb2 * 16 + ((lane >> 3) & 1) * 8 + (lane & 7)) * 128
                                               + (dp * 16 + (lane >> 4) * 8) * 2);
                const uint32_t so = sw128(off);
                uint32_t r0, r1, r2, r3;
                ldsm_x4_t(st + AT_VH + so, r0, r1, r2, r3);
                uint32_t vh0[2] = {r0, r1}, vh1[2] = {r2, r3};
                ldsm_x4_t(st + AT_VL + so, r0, r1, r2, r3);
                uint32_t vl0[2] = {r0, r1}, vl1[2] = {r2, r3};
                mma16816(of[dp * 2],     ph, vh0);
                mma16816(of[dp * 2],     pl, vh0);
                mma16816(of[dp * 2],     ph, vl0);
                mma16816(of[dp * 2 + 1], ph, vh1);
                mma16816(of[dp * 2 + 1], pl, vh1);
                mma16816(of[dp * 2 + 1], ph, vl1);
            }
        }
        __syncthreads();   // stage reuse guard
    }

    // ---- normalize, split, write ctx hi/lo ----
    const float inv0 = 1.0f / l0, inv1 = 1.0f / l1;
    const int r0g = b * L_SEQ + q0 + wm + (lane >> 2);
    const int cb  = h * DH + 2 * (lane & 3);
    #pragma unroll
    for (int j = 0; j < 8; j++) {
        const int c = cb + 8 * j;
        uint32_t hi, lo;
        split2pack(of[j][0] * inv0, of[j][1] * inv0, hi, lo);
        *reinterpret_cast<uint32_t*>(ctx_h + (size_t)r0g * DM + c) = hi;
        *reinterpret_cast<uint32_t*>(ctx_l + (size_t)r0g * DM + c) = lo;
        split2pack(of[j][2] * inv1, of[j][3] * inv1, hi, lo);
        *reinterpret_cast<uint32_t*>(ctx_h + (size_t)(r0g + 8) * DM + c) = hi;
        *reinterpret_cast<uint32_t*>(ctx_l + (size_t)(r0g + 8) * DM + c) = lo;
    }
}

// ---------------------------------------------------------------------------
// Launch
// ---------------------------------------------------------------------------
extern "C" void kernel_launch(void* const* d_in, const int* in_sizes, int n_in,
                              void* d_out, int out_size)
{
    (void)in_sizes; (void)n_in; (void)out_size;
    const float* x     = (const float*)d_in[0];
    const float* qkv_w = (const float*)d_in[1];
    const float* qkv_b = (const float*)d_in[2];
    const float* out_w = (const float*)d_in[3];
    const float* out_b = (const float*)d_in[4];
    const float* ff1_w = (const float*)d_in[5];
    const float* ff1_b = (const float*)d_in[6];
    const float* ff2_w = (const float*)d_in[7];
    const float* ff2_b = (const float*)d_in[8];
    const float* ln1_g = (const float*)d_in[9];
    const float* ln1_b = (const float*)d_in[10];
    const float* ln2_g = (const float*)d_in[11];
    const float* ln2_b = (const float*)d_in[12];
    float* out = (float*)d_out;

    __nv_bfloat16 *qhp, *qlp, *ah, *al, *bh, *bl;
    __nv_bfloat16 *w1h, *w1l, *w2h, *w2l, *w3h, *w3l, *w4h, *w4l;
    cudaGetSymbolAddress((void**)&qhp, g_qh); cudaGetSymbolAddress((void**)&qlp, g_ql);
    cudaGetSymbolAddress((void**)&ah, g_ah);  cudaGetSymbolAddress((void**)&al, g_al);
    cudaGetSymbolAddress((void**)&bh, g_bh);  cudaGetSymbolAddress((void**)&bl, g_bl);
    cudaGetSymbolAddress((void**)&w1h, g_w1h); cudaGetSymbolAddress((void**)&w1l, g_w1l);
    cudaGetSymbolAddress((void**)&w2h, g_w2h); cudaGetSymbolAddress((void**)&w2l, g_w2l);
    cudaGetSymbolAddress((void**)&w3h, g_w3h); cudaGetSymbolAddress((void**)&w3l, g_w3l);
    cudaGetSymbolAddress((void**)&w4h, g_w4h); cudaGetSymbolAddress((void**)&w4l, g_w4l);

    cudaFuncSetAttribute(attn_kernel, cudaFuncAttributeMaxDynamicSharedMemorySize, AT_SMEM);
    cudaFuncSetAttribute(tgemm_kernel<1>, cudaFuncAttributeMaxDynamicSharedMemorySize, TG_SMEM);
    cudaFuncSetAttribute(tgemm_kernel<2>, cudaFuncAttributeMaxDynamicSharedMemorySize, TG_SMEM);
    cudaFuncSetAttribute(tgemm_kernel<3>, cudaFuncAttributeMaxDynamicSharedMemorySize, TG_SMEM);

    const dim3 tb(32, 8);

    // 0) weight transpose + bf16 split
    wsplit_kernel<<<dim3(3 * DM / 32, DM / 32),  tb>>>(qkv_w, w1h, w1l, DM,  3 * DM);
    wsplit_kernel<<<dim3(DM / 32,     DM / 32),  tb>>>(out_w, w2h, w2l, DM,  DM);
    wsplit_kernel<<<dim3(FFH / 32,    DM / 32),  tb>>>(ff1_w, w3h, w3l, DM,  FFH);
    wsplit_kernel<<<dim3(DM / 32,     FFH / 32), tb>>>(ff2_w, w4h, w4l, FFH, DM);

    // 1) bufA = LN1(x)
    ln_kernel<<<NROWS, 256>>>(x, ln1_g, ln1_b, ah, al);

    // 2) qkv(hi/lo, q pre-scaled) = bufA @ qkv_w + qkv_b     [8192, 3072]
    tgemm_kernel<3><<<dim3(3 * DM / 128, NROWS / 128), 256, TG_SMEM>>>(
        ah, al, w1h, w1l, qkv_b, nullptr, nullptr, qhp, qlp, 3 * DM, DM);

    // 3) bufB = attention(qkv)  (hi/lo ctx)
    attn_kernel<<<dim3(L_SEQ / 128, BATCH * NH), 256, AT_SMEM>>>(qhp, qlp, bh, bl);

    // 4) out = x + bufB @ out_w + out_b                      [8192, 1024]
    tgemm_kernel<2><<<dim3(DM / 128, NROWS / 128), 256, TG_SMEM>>>(
        bh, bl, w2h, w2l, out_b, x, out, nullptr, nullptr, DM, DM);

    // 5) bufA = LN2(out)
    ln_kernel<<<NROWS, 256>>>(out, ln2_g, ln2_b, ah, al);

    // 6) bufB = GELU(bufA @ ff1_w + ff1_b)                   [8192, 2048]
    tgemm_kernel<1><<<dim3(FFH / 128, NROWS / 128), 256, TG_SMEM>>>(
        ah, al, w3h, w3l, ff1_b, nullptr, nullptr, bh, bl, FFH, DM);

    // 7) out = out + bufB @ ff2_w + ff2_b                    [8192, 1024]
    tgemm_kernel<2><<<dim3(DM / 128, NROWS / 128), 256, TG_SMEM>>>(
        bh, bl, w4h, w4l, ff2_b, out, out, nullptr, nullptr, DM, FFH);
}

// round 10
// speedup vs baseline: 3.7483x; 2.3277x over previous
#include <cuda_runtime.h>
#include <cuda_fp16.h>
#include <math.h>
#include <stdint.h>

// ---------------------------------------------------------------------------
// Problem constants
// ---------------------------------------------------------------------------
#define DM     1024
#define L_SEQ  2048
#define BATCH  4
#define NROWS  8192
#define NH     16
#define DH     64
#define FFH    2048

// ---------------------------------------------------------------------------
// Scratch (device globals; allocation-free per harness rules)
// ---------------------------------------------------------------------------
__device__ __half g_q [(size_t)NROWS * 3 * DM];   // qkv fp16 (q pre-scaled)
__device__ __half g_a [(size_t)NROWS * FFH];      // activation buffer A
__device__ __half g_b [(size_t)NROWS * FFH];      // activation buffer B
__device__ __half g_w1h[(size_t)3 * DM * DM], g_w1l[(size_t)3 * DM * DM];
__device__ __half g_w2h[(size_t)DM * DM],     g_w2l[(size_t)DM * DM];
__device__ __half g_w3h[(size_t)FFH * DM],    g_w3l[(size_t)FFH * DM];
__device__ __half g_w4h[(size_t)DM * FFH],    g_w4l[(size_t)DM * FFH];

// ---------------------------------------------------------------------------
// PTX helpers (portable: cp.async / ldmatrix / mma.sync only)
// ---------------------------------------------------------------------------
__device__ __forceinline__ uint32_t smem_u32(const void* p) {
    uint32_t a;
    asm("{ .reg .u64 t; cvta.to.shared.u64 t, %1; cvt.u32.u64 %0, t; }" : "=r"(a) : "l"(p));
    return a;
}
__device__ __forceinline__ void cpa16(uint32_t dst, const void* src) {
    asm volatile("cp.async.cg.shared.global [%0], [%1], 16;" :: "r"(dst), "l"(src));
}
#define CP_COMMIT() asm volatile("cp.async.commit_group;" ::: "memory")
#define CP_WAIT(n)  asm volatile("cp.async.wait_group %0;" :: "n"(n) : "memory")

__device__ __forceinline__ void ldsm_x4(uint32_t addr, uint32_t& r0, uint32_t& r1,
                                        uint32_t& r2, uint32_t& r3) {
    asm volatile("ldmatrix.sync.aligned.m8n8.x4.shared.b16 {%0,%1,%2,%3}, [%4];"
                 : "=r"(r0), "=r"(r1), "=r"(r2), "=r"(r3) : "r"(addr));
}
__device__ __forceinline__ void ldsm_x4_t(uint32_t addr, uint32_t& r0, uint32_t& r1,
                                          uint32_t& r2, uint32_t& r3) {
    asm volatile("ldmatrix.sync.aligned.m8n8.x4.trans.shared.b16 {%0,%1,%2,%3}, [%4];"
                 : "=r"(r0), "=r"(r1), "=r"(r2), "=r"(r3) : "r"(addr));
}
__device__ __forceinline__ void mma16816(float* c, const uint32_t* a, const uint32_t* b) {
    asm volatile(
        "mma.sync.aligned.m16n8k16.row.col.f32.f16.f16.f32 "
        "{%0,%1,%2,%3}, {%4,%5,%6,%7}, {%8,%9}, {%0,%1,%2,%3};"
        : "+f"(c[0]), "+f"(c[1]), "+f"(c[2]), "+f"(c[3])
        : "r"(a[0]), "r"(a[1]), "r"(a[2]), "r"(a[3]), "r"(b[0]), "r"(b[1]));
}
__device__ __forceinline__ uint32_t sw128(uint32_t off) {
    return off ^ ((off >> 3) & 0x70);
}
__device__ __forceinline__ uint32_t pack2h(float a, float b) {
    __half2 H = __floats2half2_rn(a, b);
    return *reinterpret_cast<uint32_t*>(&H);
}
// fp16 split: x = hi + lo
__device__ __forceinline__ void split2h(float a, float b, uint32_t& hi, uint32_t& lo) {
    __half2 H = __floats2half2_rn(a, b);
    const float ra = a - __half2float(__low2half(H));
    const float rb = b - __half2float(__high2half(H));
    __half2 L = __floats2half2_rn(ra, rb);
    hi = *reinterpret_cast<uint32_t*>(&H);
    lo = *reinterpret_cast<uint32_t*>(&L);
}

// ---------------------------------------------------------------------------
// Weight transpose + split: W[K,N] fp32 -> Wh/Wl [N,K] fp16 (K-major)
// ---------------------------------------------------------------------------
__global__ void wsplit_kernel(const float* __restrict__ W,
                              __half* __restrict__ Wh,
                              __half* __restrict__ Wl, int K, int N)
{
    __shared__ float t[32][33];
    const int bx = blockIdx.x, by = blockIdx.y;
    const int tx = threadIdx.x, ty = threadIdx.y;
    #pragma unroll
    for (int j = 0; j < 4; j++)
        t[ty + j * 8][tx] = W[(size_t)(by * 32 + ty + j * 8) * N + bx * 32 + tx];
    __syncthreads();
    #pragma unroll
    for (int j = 0; j < 4; j++) {
        const float v = t[tx][ty + j * 8];
        const int n = bx * 32 + ty + j * 8, k = by * 32 + tx;
        const __half h = __float2half_rn(v);
        Wh[(size_t)n * K + k] = h;
        Wl[(size_t)n * K + k] = __float2half_rn(v - __half2float(h));
    }
}

// ---------------------------------------------------------------------------
// LayerNorm -> single fp16
// ---------------------------------------------------------------------------
__global__ void ln_kernel(const float* __restrict__ x,
                          const float* __restrict__ gam,
                          const float* __restrict__ bet,
                          __half* __restrict__ o)
{
    const int row = blockIdx.x;
    const int t   = threadIdx.x;
    const float4 v = reinterpret_cast<const float4*>(x + (size_t)row * DM)[t];

    float s  = v.x + v.y + v.z + v.w;
    float ss = v.x*v.x + v.y*v.y + v.z*v.z + v.w*v.w;

    __shared__ float rs[8], rq[8];
    #pragma unroll
    for (int m = 16; m > 0; m >>= 1) {
        s  += __shfl_down_sync(0xffffffffu, s,  m);
        ss += __shfl_down_sync(0xffffffffu, ss, m);
    }
    if ((t & 31) == 0) { rs[t >> 5] = s; rq[t >> 5] = ss; }
    __syncthreads();
    if (t == 0) {
        float a = 0.f, b = 0.f;
        #pragma unroll
        for (int i = 0; i < 8; i++) { a += rs[i]; b += rq[i]; }
        rs[0] = a; rq[0] = b;
    }
    __syncthreads();

    const float mean = rs[0] * (1.0f / DM);
    const float var  = rq[0] * (1.0f / DM) - mean * mean;
    const float rstd = rsqrtf(var + 1e-5f);

    const float4 g4 = reinterpret_cast<const float4*>(gam)[t];
    const float4 b4 = reinterpret_cast<const float4*>(bet)[t];
    const float o0 = (v.x - mean) * rstd * g4.x + b4.x;
    const float o1 = (v.y - mean) * rstd * g4.y + b4.y;
    const float o2 = (v.z - mean) * rstd * g4.z + b4.z;
    const float o3 = (v.w - mean) * rstd * g4.w + b4.w;

    const size_t idx = (size_t)row * DM + t * 4;
    *reinterpret_cast<uint2*>(o + idx) = make_uint2(pack2h(o0, o1), pack2h(o2, o3));
}

// ---------------------------------------------------------------------------
// Shared tile loader: 128 rows x 64 fp16 cols, row stride 'ldg' elems, SW128.
// ---------------------------------------------------------------------------
__device__ __forceinline__ void fill_tile(uint32_t sdst, const __half* g,
                                          int row0, int k0, int ldg, int tid)
{
    #pragma unroll
    for (int i = 0; i < 4; i++) {
        const int idx = i * 256 + tid;
        const int r = idx >> 3, c = idx & 7;
        const uint32_t off = (uint32_t)(r * 128 + c * 16);
        const uint32_t so  = sdst + sw128(off);
        const char* src = (const char*)g + (((size_t)(row0 + r)) * ldg + (size_t)k0 + c * 8) * 2;
        cpa16(so, src);
    }
}

// ---------------------------------------------------------------------------
// mma.sync fp16 GEMM, weight-split 2-term: C = A_fp16 @ (Bh + Bl)^T
// 128x128 CTA tile, 8 warps (2x4), warp 64x32. K chunks of 64, double-buffered.
// EPI: 1 = +bias,GELU -> fp16 ; 2 = +bias+res -> fp32 ;
//      3 = +bias, q-cols x0.125 -> fp16 (qkv)
// ---------------------------------------------------------------------------
#define STG_A  0
#define STG_BH 16384
#define STG_BL 32768
#define STG_SZ 49152
#define TG_SMEM (2 * STG_SZ)   /* 96 KB */

template<int EPI>
__global__ __launch_bounds__(256, 1)
void tgemm_kernel(const __half* __restrict__ A,
                  const __half* __restrict__ Bh, const __half* __restrict__ Bl,
                  const float* __restrict__ bias, const float* __restrict__ res,
                  float* __restrict__ C, __half* __restrict__ Ch,
                  int N, int K)
{
    extern __shared__ char smem[];
    const uint32_t sb = smem_u32(smem);
    const int tid  = threadIdx.x;
    const int wid  = tid >> 5, lane = tid & 31;
    const int bm   = blockIdx.y, bn = blockIdx.x;
    const int wm   = (wid >> 2) * 64;
    const int wn   = (wid & 3) * 32;

    float acc[4][4][4];
    #pragma unroll
    for (int mt = 0; mt < 4; mt++)
        #pragma unroll
        for (int nt = 0; nt < 4; nt++)
            #pragma unroll
            for (int e = 0; e < 4; e++) acc[mt][nt][e] = 0.f;

    const int nch = K >> 6;

    fill_tile(sb + STG_A,  A,  bm * 128, 0, K, tid);
    fill_tile(sb + STG_BH, Bh, bn * 128, 0, K, tid);
    fill_tile(sb + STG_BL, Bl, bn * 128, 0, K, tid);
    CP_COMMIT();

    for (int ch = 0; ch < nch; ++ch) {
        if (ch + 1 < nch) {
            const uint32_t nst = sb + ((ch + 1) & 1) * STG_SZ;
            const int k1 = (ch + 1) << 6;
            fill_tile(nst + STG_A,  A,  bm * 128, k1, K, tid);
            fill_tile(nst + STG_BH, Bh, bn * 128, k1, K, tid);
            fill_tile(nst + STG_BL, Bl, bn * 128, k1, K, tid);
            CP_COMMIT();
            CP_WAIT(1);
        } else {
            CP_WAIT(0);
        }
        __syncthreads();

        const uint32_t st = sb + (ch & 1) * STG_SZ;
        #pragma unroll
        for (int ks = 0; ks < 4; ks++) {
            const uint32_t kb = (uint32_t)(ks * 32 + ((lane >> 4) << 4));
            uint32_t af[4][4], bh[4][2], bl[4][2];
            #pragma unroll
            for (int mt = 0; mt < 4; mt++) {
                const uint32_t off = (uint32_t)((wm + mt * 16 + (lane & 15)) * 128) + kb;
                const uint32_t so  = sw128(off);
                ldsm_x4(st + STG_A + so, af[mt][0], af[mt][1], af[mt][2], af[mt][3]);
            }
            #pragma unroll
            for (int np = 0; np < 2; np++) {
                const uint32_t off = (uint32_t)((wn + np * 16 + (lane & 15)) * 128) + kb;
                const uint32_t so  = sw128(off);
                uint32_t r0, r1, r2, r3;
                ldsm_x4(st + STG_BH + so, r0, r1, r2, r3);
                bh[np * 2][0] = r0; bh[np * 2 + 1][0] = r1;
                bh[np * 2][1] = r2; bh[np * 2 + 1][1] = r3;
                ldsm_x4(st + STG_BL + so, r0, r1, r2, r3);
                bl[np * 2][0] = r0; bl[np * 2 + 1][0] = r1;
                bl[np * 2][1] = r2; bl[np * 2 + 1][1] = r3;
            }
            #pragma unroll
            for (int mt = 0; mt < 4; mt++)
                #pragma unroll
                for (int nt = 0; nt < 4; nt++) {
                    mma16816(acc[mt][nt], af[mt], bh[nt]);
                    mma16816(acc[mt][nt], af[mt], bl[nt]);
                }
        }
        __syncthreads();
    }

    const int rbase = bm * 128 + wm + (lane >> 2);
    const int cbase = bn * 128 + wn + (lane & 3) * 2;
    #pragma unroll
    for (int mt = 0; mt < 4; mt++) {
        #pragma unroll
        for (int half = 0; half < 2; half++) {
            const int r = rbase + mt * 16 + half * 8;
            const size_t rowoff = (size_t)r * N;
            #pragma unroll
            for (int nt = 0; nt < 4; nt++) {
                const int c = cbase + nt * 8;
                float v0 = acc[mt][nt][half * 2 + 0] + __ldg(bias + c);
                float v1 = acc[mt][nt][half * 2 + 1] + __ldg(bias + c + 1);
                if (EPI == 2) {
                    const float2 rv = *reinterpret_cast<const float2*>(res + rowoff + c);
                    v0 += rv.x; v1 += rv.y;
                    *reinterpret_cast<float2*>(C + rowoff + c) = make_float2(v0, v1);
                } else if (EPI == 1) {
                    v0 = 0.5f * v0 * (1.0f + erff(v0 * 0.70710678118654752f));
                    v1 = 0.5f * v1 * (1.0f + erff(v1 * 0.70710678118654752f));
                    *reinterpret_cast<uint32_t*>(Ch + rowoff + c) = pack2h(v0, v1);
                } else {  // EPI == 3
                    const float sc = (c < DM) ? 0.125f : 1.0f;  // q-scale, exact
                    *reinterpret_cast<uint32_t*>(Ch + rowoff + c) = pack2h(v0 * sc, v1 * sc);
                }
            }
        }
    }
}

// ---------------------------------------------------------------------------
// Tensor-core flash attention, fp16 (S 1-term, P@V 2-term with P hi/lo).
// CTA = 128 q-rows x (b,h); 8 warps x 16 rows. KV tiles of 128, double-buffered.
// ---------------------------------------------------------------------------
#define AT_Q    0
#define AT_STG  16384
#define AT_K    0
#define AT_V    16384
#define AT_STG_SZ 32768
#define AT_SMEM (AT_STG + 2 * AT_STG_SZ)   /* 80 KB */

__global__ __launch_bounds__(256, 1)
void attn_kernel(const __half* __restrict__ qkv, __half* __restrict__ ctx)
{
    extern __shared__ char smem[];
    const uint32_t sb = smem_u32(smem);
    const int tid  = threadIdx.x;
    const int wid  = tid >> 5, lane = tid & 31;
    const int b    = blockIdx.y >> 4, h = blockIdx.y & 15;
    const int q0   = blockIdx.x * 128;
    const int wm   = wid * 16;

    const int qcol = h * DH;
    const int kcol = DM + h * DH;
    const int vcol = 2 * DM + h * DH;
    const int rowQ = b * L_SEQ + q0;
    const int rowB = b * L_SEQ;

    fill_tile(sb + AT_Q, qkv, rowQ, qcol, 3 * DM, tid);
    fill_tile(sb + AT_STG + AT_K, qkv, rowB, kcol, 3 * DM, tid);
    fill_tile(sb + AT_STG + AT_V, qkv, rowB, vcol, 3 * DM, tid);
    CP_COMMIT();

    uint32_t qf[4][4];
    float m0 = -3.0e38f, m1 = -3.0e38f, l0 = 0.f, l1 = 0.f;
    float of[8][4];
    #pragma unroll
    for (int j = 0; j < 8; j++)
        #pragma unroll
        for (int e = 0; e < 4; e++) of[j][e] = 0.f;

    for (int t = 0; t < L_SEQ / 128; t++) {
        if (t + 1 < L_SEQ / 128) {
            const uint32_t nst = sb + AT_STG + ((t + 1) & 1) * AT_STG_SZ;
            const int rk = rowB + (t + 1) * 128;
            fill_tile(nst + AT_K, qkv, rk, kcol, 3 * DM, tid);
            fill_tile(nst + AT_V, qkv, rk, vcol, 3 * DM, tid);
            CP_COMMIT();
            CP_WAIT(1);
        } else {
            CP_WAIT(0);
        }
        __syncthreads();

        if (t == 0) {
            #pragma unroll
            for (int kb = 0; kb < 4; kb++) {
                const uint32_t off = (uint32_t)((wm + (lane & 15)) * 128 + kb * 32
                                               + ((lane >> 4) << 4));
                const uint32_t so = sw128(off);
                ldsm_x4(sb + AT_Q + so, qf[kb][0], qf[kb][1], qf[kb][2], qf[kb][3]);
            }
        }

        const uint32_t st = sb + AT_STG + (t & 1) * AT_STG_SZ;

        // ---- S = Q @ K^T (single term) ----
        float sf[16][4];
        #pragma unroll
        for (int j = 0; j < 16; j++)
            #pragma unroll
            for (int e = 0; e < 4; e++) sf[j][e] = 0.f;

        #pragma unroll
        for (int kb = 0; kb < 4; kb++)
            #pragma unroll
            for (int np = 0; np < 8; np++) {
                const uint32_t off = (uint32_t)((np * 16 + (lane & 15)) * 128 + kb * 32
                                               + ((lane >> 4) << 4));
                const uint32_t so = sw128(off);
                uint32_t r0, r1, r2, r3;
                ldsm_x4(st + AT_K + so, r0, r1, r2, r3);
                uint32_t k0[2] = {r0, r2}, k1[2] = {r1, r3};
                mma16816(sf[2 * np],     qf[kb], k0);
                mma16816(sf[2 * np + 1], qf[kb], k1);
            }

        // ---- online softmax on fragments ----
        float mt0 = -3.0e38f, mt1 = -3.0e38f;
        #pragma unroll
        for (int j = 0; j < 16; j++) {
            mt0 = fmaxf(mt0, fmaxf(sf[j][0], sf[j][1]));
            mt1 = fmaxf(mt1, fmaxf(sf[j][2], sf[j][3]));
        }
        mt0 = fmaxf(mt0, __shfl_xor_sync(0xffffffffu, mt0, 1));
        mt0 = fmaxf(mt0, __shfl_xor_sync(0xffffffffu, mt0, 2));
        mt1 = fmaxf(mt1, __shfl_xor_sync(0xffffffffu, mt1, 1));
        mt1 = fmaxf(mt1, __shfl_xor_sync(0xffffffffu, mt1, 2));

        const float mn0 = fmaxf(m0, mt0), mn1 = fmaxf(m1, mt1);
        const float cr0 = __expf(m0 - mn0), cr1 = __expf(m1 - mn1);
        m0 = mn0; m1 = mn1;

        float rs0 = 0.f, rs1 = 0.f;
        #pragma unroll
        for (int j = 0; j < 16; j++) {
            sf[j][0] = __expf(sf[j][0] - mn0);
            sf[j][1] = __expf(sf[j][1] - mn0);
            sf[j][2] = __expf(sf[j][2] - mn1);
            sf[j][3] = __expf(sf[j][3] - mn1);
            rs0 += sf[j][0] + sf[j][1];
            rs1 += sf[j][2] + sf[j][3];
        }
        rs0 += __shfl_xor_sync(0xffffffffu, rs0, 1);
        rs0 += __shfl_xor_sync(0xffffffffu, rs0, 2);
        rs1 += __shfl_xor_sync(0xffffffffu, rs1, 1);
        rs1 += __shfl_xor_sync(0xffffffffu, rs1, 2);
        l0 = l0 * cr0 + rs0;
        l1 = l1 * cr1 + rs1;
        #pragma unroll
        for (int j = 0; j < 8; j++) {
            of[j][0] *= cr0; of[j][1] *= cr0;
            of[j][2] *= cr1; of[j][3] *= cr1;
        }

        // ---- O += (Ph + Pl) @ V ----
        #pragma unroll
        for (int kb2 = 0; kb2 < 8; kb2++) {
            uint32_t ph[4], pl[4];
            split2h(sf[2 * kb2][0],     sf[2 * kb2][1],     ph[0], pl[0]);
            split2h(sf[2 * kb2][2],     sf[2 * kb2][3],     ph[1], pl[1]);
            split2h(sf[2 * kb2 + 1][0], sf[2 * kb2 + 1][1], ph[2], pl[2]);
            split2h(sf[2 * kb2 + 1][2], sf[2 * kb2 + 1][3], ph[3], pl[3]);
            #pragma unroll
            for (int dp = 0; dp < 4; dp++) {
                const uint32_t off = (uint32_t)((kb2 * 16 + ((lane >> 3) & 1) * 8 + (lane & 7)) * 128
                                               + (dp * 16 + (lane >> 4) * 8) * 2);
                const uint32_t so = sw128(off);
                uint32_t r0, r1, r2, r3;
                ldsm_x4_t(st + AT_V + so, r0, r1, r2, r3);
                uint32_t v0[2] = {r0, r1}, v1[2] = {r2, r3};
                mma16816(of[dp * 2],     ph, v0);
                mma16816(of[dp * 2],     pl, v0);
                mma16816(of[dp * 2 + 1], ph, v1);
                mma16816(of[dp * 2 + 1], pl, v1);
            }
        }
        __syncthreads();
    }

    // ---- normalize + write ctx fp16 ----
    const float inv0 = 1.0f / l0, inv1 = 1.0f / l1;
    const int r0g = b * L_SEQ + q0 + wm + (lane >> 2);
    const int cb  = h * DH + 2 * (lane & 3);
    #pragma unroll
    for (int j = 0; j < 8; j++) {
        const int c = cb + 8 * j;
        *reinterpret_cast<uint32_t*>(ctx + (size_t)r0g * DM + c) =
            pack2h(of[j][0] * inv0, of[j][1] * inv0);
        *reinterpret_cast<uint32_t*>(ctx + (size_t)(r0g + 8) * DM + c) =
            pack2h(of[j][2] * inv1, of[j][3] * inv1);
    }
}

// ---------------------------------------------------------------------------
// Launch
// ---------------------------------------------------------------------------
extern "C" void kernel_launch(void* const* d_in, const int* in_sizes, int n_in,
                              void* d_out, int out_size)
{
    (void)in_sizes; (void)n_in; (void)out_size;
    const float* x     = (const float*)d_in[0];
    const float* qkv_w = (const float*)d_in[1];
    const float* qkv_b = (const float*)d_in[2];
    const float* out_w = (const float*)d_in[3];
    const float* out_b = (const float*)d_in[4];
    const float* ff1_w = (const float*)d_in[5];
    const float* ff1_b = (const float*)d_in[6];
    const float* ff2_w = (const float*)d_in[7];
    const float* ff2_b = (const float*)d_in[8];
    const float* ln1_g = (const float*)d_in[9];
    const float* ln1_b = (const float*)d_in[10];
    const float* ln2_g = (const float*)d_in[11];
    const float* ln2_b = (const float*)d_in[12];
    float* out = (float*)d_out;

    __half *q, *a, *bbuf;
    __half *w1h, *w1l, *w2h, *w2l, *w3h, *w3l, *w4h, *w4l;
    cudaGetSymbolAddress((void**)&q, g_q);
    cudaGetSymbolAddress((void**)&a, g_a);
    cudaGetSymbolAddress((void**)&bbuf, g_b);
    cudaGetSymbolAddress((void**)&w1h, g_w1h); cudaGetSymbolAddress((void**)&w1l, g_w1l);
    cudaGetSymbolAddress((void**)&w2h, g_w2h); cudaGetSymbolAddress((void**)&w2l, g_w2l);
    cudaGetSymbolAddress((void**)&w3h, g_w3h); cudaGetSymbolAddress((void**)&w3l, g_w3l);
    cudaGetSymbolAddress((void**)&w4h, g_w4h); cudaGetSymbolAddress((void**)&w4l, g_w4l);

    cudaFuncSetAttribute(attn_kernel, cudaFuncAttributeMaxDynamicSharedMemorySize, AT_SMEM);
    cudaFuncSetAttribute(tgemm_kernel<1>, cudaFuncAttributeMaxDynamicSharedMemorySize, TG_SMEM);
    cudaFuncSetAttribute(tgemm_kernel<2>, cudaFuncAttributeMaxDynamicSharedMemorySize, TG_SMEM);
    cudaFuncSetAttribute(tgemm_kernel<3>, cudaFuncAttributeMaxDynamicSharedMemorySize, TG_SMEM);

    const dim3 tb(32, 8);

    // 0) weight transpose + fp16 split
    wsplit_kernel<<<dim3(3 * DM / 32, DM / 32),  tb>>>(qkv_w, w1h, w1l, DM,  3 * DM);
    wsplit_kernel<<<dim3(DM / 32,     DM / 32),  tb>>>(out_w, w2h, w2l, DM,  DM);
    wsplit_kernel<<<dim3(FFH / 32,    DM / 32),  tb>>>(ff1_w, w3h, w3l, DM,  FFH);
    wsplit_kernel<<<dim3(DM / 32,     FFH / 32), tb>>>(ff2_w, w4h, w4l, FFH, DM);

    // 1) bufA = LN1(x)  (fp16)
    ln_kernel<<<NROWS, 256>>>(x, ln1_g, ln1_b, a);

    // 2) qkv(fp16, q pre-scaled) = bufA @ qkv_w + qkv_b     [8192, 3072]
    tgemm_kernel<3><<<dim3(3 * DM / 128, NROWS / 128), 256, TG_SMEM>>>(
        a, w1h, w1l, qkv_b, nullptr, nullptr, q, 3 * DM, DM);

    // 3) bufB = attention(qkv)  (fp16 ctx)
    attn_kernel<<<dim3(L_SEQ / 128, BATCH * NH), 256, AT_SMEM>>>(q, bbuf);

    // 4) out = x + bufB @ out_w + out_b                     [8192, 1024]
    tgemm_kernel<2><<<dim3(DM / 128, NROWS / 128), 256, TG_SMEM>>>(
        bbuf, w2h, w2l, out_b, x, out, nullptr, DM, DM);

    // 5) bufA = LN2(out)
    ln_kernel<<<NROWS, 256>>>(out, ln2_g, ln2_b, a);

    // 6) bufB = GELU(bufA @ ff1_w + ff1_b)                  [8192, 2048]
    tgemm_kernel<1><<<dim3(FFH / 128, NROWS / 128), 256, TG_SMEM>>>(
        a, w3h, w3l, ff1_b, nullptr, nullptr, bbuf, FFH, DM);

    // 7) out = out + bufB @ ff2_w + ff2_b                   [8192, 1024]
    tgemm_kernel<2><<<dim3(DM / 128, NROWS / 128), 256, TG_SMEM>>>(
        bbuf, w4h, w4l, ff2_b, out, out, nullptr, DM, FFH);
}

// round 12
// speedup vs baseline: 5.3378x; 1.4240x over previous
#include <cuda_runtime.h>
#include <cuda_fp16.h>
#include <math.h>
#include <stdint.h>

// ---------------------------------------------------------------------------
// Problem constants
// ---------------------------------------------------------------------------
#define DM     1024
#define L_SEQ  2048
#define BATCH  4
#define NROWS  8192
#define NH     16
#define DH     64
#define FFH    2048

// ---------------------------------------------------------------------------
// Scratch (device globals; allocation-free per harness rules)
// ---------------------------------------------------------------------------
__device__ __half g_q [(size_t)NROWS * 3 * DM];   // qkv fp16 (q pre-scaled)
__device__ __half g_a [(size_t)NROWS * FFH];      // activation buffer A
__device__ __half g_b [(size_t)NROWS * FFH];      // activation buffer B
__device__ __half g_w1[(size_t)3 * DM * DM];
__device__ __half g_w2[(size_t)DM * DM];
__device__ __half g_w3[(size_t)FFH * DM];
__device__ __half g_w4[(size_t)DM * FFH];

// ---------------------------------------------------------------------------
// PTX helpers (portable: cp.async / ldmatrix / mma.sync only)
// ---------------------------------------------------------------------------
__device__ __forceinline__ uint32_t smem_u32(const void* p) {
    uint32_t a;
    asm("{ .reg .u64 t; cvta.to.shared.u64 t, %1; cvt.u32.u64 %0, t; }" : "=r"(a) : "l"(p));
    return a;
}
__device__ __forceinline__ void cpa16(uint32_t dst, const void* src) {
    asm volatile("cp.async.cg.shared.global [%0], [%1], 16;" :: "r"(dst), "l"(src));
}
#define CP_COMMIT() asm volatile("cp.async.commit_group;" ::: "memory")
#define CP_WAIT(n)  asm volatile("cp.async.wait_group %0;" :: "n"(n) : "memory")

__device__ __forceinline__ void ldsm_x4(uint32_t addr, uint32_t& r0, uint32_t& r1,
                                        uint32_t& r2, uint32_t& r3) {
    asm volatile("ldmatrix.sync.aligned.m8n8.x4.shared.b16 {%0,%1,%2,%3}, [%4];"
                 : "=r"(r0), "=r"(r1), "=r"(r2), "=r"(r3) : "r"(addr));
}
__device__ __forceinline__ void ldsm_x4_t(uint32_t addr, uint32_t& r0, uint32_t& r1,
                                          uint32_t& r2, uint32_t& r3) {
    asm volatile("ldmatrix.sync.aligned.m8n8.x4.trans.shared.b16 {%0,%1,%2,%3}, [%4];"
                 : "=r"(r0), "=r"(r1), "=r"(r2), "=r"(r3) : "r"(addr));
}
__device__ __forceinline__ void mma16816(float* c, const uint32_t* a, const uint32_t* b) {
    asm volatile(
        "mma.sync.aligned.m16n8k16.row.col.f32.f16.f16.f32 "
        "{%0,%1,%2,%3}, {%4,%5,%6,%7}, {%8,%9}, {%0,%1,%2,%3};"
        : "+f"(c[0]), "+f"(c[1]), "+f"(c[2]), "+f"(c[3])
        : "r"(a[0]), "r"(a[1]), "r"(a[2]), "r"(a[3]), "r"(b[0]), "r"(b[1]));
}
__device__ __forceinline__ uint32_t sw128(uint32_t off) {
    return off ^ ((off >> 3) & 0x70);
}
__device__ __forceinline__ uint32_t pack2h(float a, float b) {
    __half2 H = __floats2half2_rn(a, b);
    return *reinterpret_cast<uint32_t*>(&H);
}
// fp16 split: x = hi + lo
__device__ __forceinline__ void split2h(float a, float b, uint32_t& hi, uint32_t& lo) {
    __half2 H = __floats2half2_rn(a, b);
    const float ra = a - __half2float(__low2half(H));
    const float rb = b - __half2float(__high2half(H));
    __half2 L = __floats2half2_rn(ra, rb);
    hi = *reinterpret_cast<uint32_t*>(&H);
    lo = *reinterpret_cast<uint32_t*>(&L);
}

// ---------------------------------------------------------------------------
// Weight transpose: W[K,N] fp32 -> Wt[N,K] fp16 (K-major)
// ---------------------------------------------------------------------------
__global__ void wconv_kernel(const float* __restrict__ W,
                             __half* __restrict__ Wt, int K, int N)
{
    __shared__ float t[32][33];
    const int bx = blockIdx.x, by = blockIdx.y;
    const int tx = threadIdx.x, ty = threadIdx.y;
    #pragma unroll
    for (int j = 0; j < 4; j++)
        t[ty + j * 8][tx] = W[(size_t)(by * 32 + ty + j * 8) * N + bx * 32 + tx];
    __syncthreads();
    #pragma unroll
    for (int j = 0; j < 4; j++) {
        const float v = t[tx][ty + j * 8];
        const int n = bx * 32 + ty + j * 8, k = by * 32 + tx;
        Wt[(size_t)n * K + k] = __float2half_rn(v);
    }
}

// ---------------------------------------------------------------------------
// LayerNorm -> fp16
// ---------------------------------------------------------------------------
__global__ void ln_kernel(const float* __restrict__ x,
                          const float* __restrict__ gam,
                          const float* __restrict__ bet,
                          __half* __restrict__ o)
{
    const int row = blockIdx.x;
    const int t   = threadIdx.x;
    const float4 v = reinterpret_cast<const float4*>(x + (size_t)row * DM)[t];

    float s  = v.x + v.y + v.z + v.w;
    float ss = v.x*v.x + v.y*v.y + v.z*v.z + v.w*v.w;

    __shared__ float rs[8], rq[8];
    #pragma unroll
    for (int m = 16; m > 0; m >>= 1) {
        s  += __shfl_down_sync(0xffffffffu, s,  m);
        ss += __shfl_down_sync(0xffffffffu, ss, m);
    }
    if ((t & 31) == 0) { rs[t >> 5] = s; rq[t >> 5] = ss; }
    __syncthreads();
    if (t == 0) {
        float a = 0.f, b = 0.f;
        #pragma unroll
        for (int i = 0; i < 8; i++) { a += rs[i]; b += rq[i]; }
        rs[0] = a; rq[0] = b;
    }
    __syncthreads();

    const float mean = rs[0] * (1.0f / DM);
    const float var  = rq[0] * (1.0f / DM) - mean * mean;
    const float rstd = rsqrtf(var + 1e-5f);

    const float4 g4 = reinterpret_cast<const float4*>(gam)[t];
    const float4 b4 = reinterpret_cast<const float4*>(bet)[t];
    const float o0 = (v.x - mean) * rstd * g4.x + b4.x;
    const float o1 = (v.y - mean) * rstd * g4.y + b4.y;
    const float o2 = (v.z - mean) * rstd * g4.z + b4.z;
    const float o3 = (v.w - mean) * rstd * g4.w + b4.w;

    const size_t idx = (size_t)row * DM + t * 4;
    *reinterpret_cast<uint2*>(o + idx) = make_uint2(pack2h(o0, o1), pack2h(o2, o3));
}

// ---------------------------------------------------------------------------
// Shared tile loader: 128 rows x 64 fp16 cols, row stride 'ldg' elems, SW128.
// ---------------------------------------------------------------------------
__device__ __forceinline__ void fill_tile(uint32_t sdst, const __half* g,
                                          int row0, int k0, int ldg, int tid)
{
    #pragma unroll
    for (int i = 0; i < 4; i++) {
        const int idx = i * 256 + tid;
        const int r = idx >> 3, c = idx & 7;
        const uint32_t off = (uint32_t)(r * 128 + c * 16);
        const uint32_t so  = sdst + sw128(off);
        const char* src = (const char*)g + (((size_t)(row0 + r)) * ldg + (size_t)k0 + c * 8) * 2;
        cpa16(so, src);
    }
}

// ---------------------------------------------------------------------------
// mma.sync fp16 GEMM (single-term): C = A @ Wt^T
// 128x128 CTA tile, 8 warps (2x4), warp 64x32. K chunks of 64, 3-stage pipeline.
// EPI: 1 = +bias,GELU -> fp16 ; 2 = +bias+res -> fp32 ;
//      3 = +bias, q-cols x0.125 -> fp16 (qkv)
// ---------------------------------------------------------------------------
#define STG_A  0
#define STG_B  16384
#define STG_SZ 32768
#define TG_SMEM (3 * STG_SZ)   /* 96 KB */

template<int EPI>
__global__ __launch_bounds__(256, 1)
void tgemm_kernel(const __half* __restrict__ A, const __half* __restrict__ B,
                  const float* __restrict__ bias, const float* __restrict__ res,
                  float* __restrict__ C, __half* __restrict__ Ch,
                  int N, int K)
{
    extern __shared__ char smem[];
    const uint32_t sb = smem_u32(smem);
    const int tid  = threadIdx.x;
    const int wid  = tid >> 5, lane = tid & 31;
    const int bm   = blockIdx.y, bn = blockIdx.x;
    const int wm   = (wid >> 2) * 64;
    const int wn   = (wid & 3) * 32;

    float acc[4][4][4];
    #pragma unroll
    for (int mt = 0; mt < 4; mt++)
        #pragma unroll
        for (int nt = 0; nt < 4; nt++)
            #pragma unroll
            for (int e = 0; e < 4; e++) acc[mt][nt][e] = 0.f;

    const int nch = K >> 6;

    // prologue: stages 0, 1
    fill_tile(sb + STG_A, A, bm * 128, 0, K, tid);
    fill_tile(sb + STG_B, B, bn * 128, 0, K, tid);
    CP_COMMIT();
    if (nch > 1) {
        fill_tile(sb + STG_SZ + STG_A, A, bm * 128, 64, K, tid);
        fill_tile(sb + STG_SZ + STG_B, B, bn * 128, 64, K, tid);
        CP_COMMIT();
    }

    int slot = 0;
    for (int ch = 0; ch < nch; ++ch) {
        if (ch + 2 < nch) {
            int ns = slot + 2;                 // (slot + 2) mod 3 — FIXED wrap
            if (ns >= 3) ns -= 3;
            const uint32_t nst = sb + ns * STG_SZ;
            const int k1 = (ch + 2) << 6;
            fill_tile(nst + STG_A, A, bm * 128, k1, K, tid);
            fill_tile(nst + STG_B, B, bn * 128, k1, K, tid);
            CP_COMMIT();
            CP_WAIT(2);
        } else if (ch + 1 < nch) {
            CP_WAIT(1);
        } else {
            CP_WAIT(0);
        }
        __syncthreads();

        const uint32_t st = sb + slot * STG_SZ;
        #pragma unroll
        for (int ks = 0; ks < 4; ks++) {
            const uint32_t kb = (uint32_t)(ks * 32 + ((lane >> 4) << 4));
            uint32_t af[4][4], bf[4][2];
            #pragma unroll
            for (int mt = 0; mt < 4; mt++) {
                const uint32_t off = (uint32_t)((wm + mt * 16 + (lane & 15)) * 128) + kb;
                const uint32_t so  = sw128(off);
                ldsm_x4(st + STG_A + so, af[mt][0], af[mt][1], af[mt][2], af[mt][3]);
            }
            #pragma unroll
            for (int np = 0; np < 2; np++) {
                const uint32_t off = (uint32_t)((wn + np * 16 + (lane & 15)) * 128) + kb;
                const uint32_t so  = sw128(off);
                uint32_t r0, r1, r2, r3;
                ldsm_x4(st + STG_B + so, r0, r1, r2, r3);
                bf[np * 2][0] = r0; bf[np * 2 + 1][0] = r1;
                bf[np * 2][1] = r2; bf[np * 2 + 1][1] = r3;
            }
            #pragma unroll
            for (int mt = 0; mt < 4; mt++)
                #pragma unroll
                for (int nt = 0; nt < 4; nt++)
                    mma16816(acc[mt][nt], af[mt], bf[nt]);
        }
        __syncthreads();
        slot = (slot + 1 == 3) ? 0 : slot + 1;
    }

    const int rbase = bm * 128 + wm + (lane >> 2);
    const int cbase = bn * 128 + wn + (lane & 3) * 2;
    #pragma unroll
    for (int mt = 0; mt < 4; mt++) {
        #pragma unroll
        for (int half = 0; half < 2; half++) {
            const int r = rbase + mt * 16 + half * 8;
            const size_t rowoff = (size_t)r * N;
            #pragma unroll
            for (int nt = 0; nt < 4; nt++) {
                const int c = cbase + nt * 8;
                float v0 = acc[mt][nt][half * 2 + 0] + __ldg(bias + c);
                float v1 = acc[mt][nt][half * 2 + 1] + __ldg(bias + c + 1);
                if (EPI == 2) {
                    const float2 rv = *reinterpret_cast<const float2*>(res + rowoff + c);
                    v0 += rv.x; v1 += rv.y;
                    *reinterpret_cast<float2*>(C + rowoff + c) = make_float2(v0, v1);
                } else if (EPI == 1) {
                    v0 = 0.5f * v0 * (1.0f + erff(v0 * 0.70710678118654752f));
                    v1 = 0.5f * v1 * (1.0f + erff(v1 * 0.70710678118654752f));
                    *reinterpret_cast<uint32_t*>(Ch + rowoff + c) = pack2h(v0, v1);
                } else {  // EPI == 3
                    const float sc = (c < DM) ? 0.125f : 1.0f;  // q-scale, exact
                    *reinterpret_cast<uint32_t*>(Ch + rowoff + c) = pack2h(v0 * sc, v1 * sc);
                }
            }
        }
    }
}

// ---------------------------------------------------------------------------
// Tensor-core flash attention, fp16 (S 1-term, P@V 2-term with P hi/lo).
// CTA = 128 q-rows x (b,h); 8 warps x 16 rows. KV tiles of 128, double-buffered.
// ---------------------------------------------------------------------------
#define AT_Q    0
#define AT_STG  16384
#define AT_K    0
#define AT_V    16384
#define AT_STG_SZ 32768
#define AT_SMEM (AT_STG + 2 * AT_STG_SZ)   /* 80 KB */

__global__ __launch_bounds__(256, 1)
void attn_kernel(const __half* __restrict__ qkv, __half* __restrict__ ctx)
{
    extern __shared__ char smem[];
    const uint32_t sb = smem_u32(smem);
    const int tid  = threadIdx.x;
    const int wid  = tid >> 5, lane = tid & 31;
    const int b    = blockIdx.y >> 4, h = blockIdx.y & 15;
    const int q0   = blockIdx.x * 128;
    const int wm   = wid * 16;

    const int qcol = h * DH;
    const int kcol = DM + h * DH;
    const int vcol = 2 * DM + h * DH;
    const int rowQ = b * L_SEQ + q0;
    const int rowB = b * L_SEQ;

    fill_tile(sb + AT_Q, qkv, rowQ, qcol, 3 * DM, tid);
    fill_tile(sb + AT_STG + AT_K, qkv, rowB, kcol, 3 * DM, tid);
    fill_tile(sb + AT_STG + AT_V, qkv, rowB, vcol, 3 * DM, tid);
    CP_COMMIT();

    uint32_t qf[4][4];
    float m0 = -3.0e38f, m1 = -3.0e38f, l0 = 0.f, l1 = 0.f;
    float of[8][4];
    #pragma unroll
    for (int j = 0; j < 8; j++)
        #pragma unroll
        for (int e = 0; e < 4; e++) of[j][e] = 0.f;

    for (int t = 0; t < L_SEQ / 128; t++) {
        if (t + 1 < L_SEQ / 128) {
            const uint32_t nst = sb + AT_STG + ((t + 1) & 1) * AT_STG_SZ;
            const int rk = rowB + (t + 1) * 128;
            fill_tile(nst + AT_K, qkv, rk, kcol, 3 * DM, tid);
            fill_tile(nst + AT_V, qkv, rk, vcol, 3 * DM, tid);
            CP_COMMIT();
            CP_WAIT(1);
        } else {
            CP_WAIT(0);
        }
        __syncthreads();

        if (t == 0) {
            #pragma unroll
            for (int kb = 0; kb < 4; kb++) {
                const uint32_t off = (uint32_t)((wm + (lane & 15)) * 128 + kb * 32
                                               + ((lane >> 4) << 4));
                const uint32_t so = sw128(off);
                ldsm_x4(sb + AT_Q + so, qf[kb][0], qf[kb][1], qf[kb][2], qf[kb][3]);
            }
        }

        const uint32_t st = sb + AT_STG + (t & 1) * AT_STG_SZ;

        // ---- S = Q @ K^T (single term) ----
        float sf[16][4];
        #pragma unroll
        for (int j = 0; j < 16; j++)
            #pragma unroll
            for (int e = 0; e < 4; e++) sf[j][e] = 0.f;

        #pragma unroll
        for (int kb = 0; kb < 4; kb++)
            #pragma unroll
            for (int np = 0; np < 8; np++) {
                const uint32_t off = (uint32_t)((np * 16 + (lane & 15)) * 128 + kb * 32
                                               + ((lane >> 4) << 4));
                const uint32_t so = sw128(off);
                uint32_t r0, r1, r2, r3;
                ldsm_x4(st + AT_K + so, r0, r1, r2, r3);
                uint32_t k0[2] = {r0, r2}, k1[2] = {r1, r3};
                mma16816(sf[2 * np],     qf[kb], k0);
                mma16816(sf[2 * np + 1], qf[kb], k1);
            }

        // ---- online softmax on fragments ----
        float mt0 = -3.0e38f, mt1 = -3.0e38f;
        #pragma unroll
        for (int j = 0; j < 16; j++) {
            mt0 = fmaxf(mt0, fmaxf(sf[j][0], sf[j][1]));
            mt1 = fmaxf(mt1, fmaxf(sf[j][2], sf[j][3]));
        }
        mt0 = fmaxf(mt0, __shfl_xor_sync(0xffffffffu, mt0, 1));
        mt0 = fmaxf(mt0, __shfl_xor_sync(0xffffffffu, mt0, 2));
        mt1 = fmaxf(mt1, __shfl_xor_sync(0xffffffffu, mt1, 1));
        mt1 = fmaxf(mt1, __shfl_xor_sync(0xffffffffu, mt1, 2));

        const float mn0 = fmaxf(m0, mt0), mn1 = fmaxf(m1, mt1);
        const float cr0 = __expf(m0 - mn0), cr1 = __expf(m1 - mn1);
        m0 = mn0; m1 = mn1;

        float rs0 = 0.f, rs1 = 0.f;
        #pragma unroll
        for (int j = 0; j < 16; j++) {
            sf[j][0] = __expf(sf[j][0] - mn0);
            sf[j][1] = __expf(sf[j][1] - mn0);
            sf[j][2] = __expf(sf[j][2] - mn1);
            sf[j][3] = __expf(sf[j][3] - mn1);
            rs0 += sf[j][0] + sf[j][1];
            rs1 += sf[j][2] + sf[j][3];
        }
        rs0 += __shfl_xor_sync(0xffffffffu, rs0, 1);
        rs0 += __shfl_xor_sync(0xffffffffu, rs0, 2);
        rs1 += __shfl_xor_sync(0xffffffffu, rs1, 1);
        rs1 += __shfl_xor_sync(0xffffffffu, rs1, 2);
        l0 = l0 * cr0 + rs0;
        l1 = l1 * cr1 + rs1;
        #pragma unroll
        for (int j = 0; j < 8; j++) {
            of[j][0] *= cr0; of[j][1] *= cr0;
            of[j][2] *= cr1; of[j][3] *= cr1;
        }

        // ---- O += (Ph + Pl) @ V ----
        #pragma unroll
        for (int kb2 = 0; kb2 < 8; kb2++) {
            uint32_t ph[4], pl[4];
            split2h(sf[2 * kb2][0],     sf[2 * kb2][1],     ph[0], pl[0]);
            split2h(sf[2 * kb2][2],     sf[2 * kb2][3],     ph[1], pl[1]);
            split2h(sf[2 * kb2 + 1][0], sf[2 * kb2 + 1][1], ph[2], pl[2]);
            split2h(sf[2 * kb2 + 1][2], sf[2 * kb2 + 1][3], ph[3], pl[3]);
            #pragma unroll
            for (int dp = 0; dp < 4; dp++) {
                const uint32_t off = (uint32_t)((kb2 * 16 + ((lane >> 3) & 1) * 8 + (lane & 7)) * 128
                                               + (dp * 16 + (lane >> 4) * 8) * 2);
                const uint32_t so = sw128(off);
                uint32_t r0, r1, r2, r3;
                ldsm_x4_t(st + AT_V + so, r0, r1, r2, r3);
                uint32_t v0[2] = {r0, r1}, v1[2] = {r2, r3};
                mma16816(of[dp * 2],     ph, v0);
                mma16816(of[dp * 2],     pl, v0);
                mma16816(of[dp * 2 + 1], ph, v1);
                mma16816(of[dp * 2 + 1], pl, v1);
            }
        }
        __syncthreads();
    }

    // ---- normalize + write ctx fp16 ----
    const float inv0 = 1.0f / l0, inv1 = 1.0f / l1;
    const int r0g = b * L_SEQ + q0 + wm + (lane >> 2);
    const int cb  = h * DH + 2 * (lane & 3);
    #pragma unroll
    for (int j = 0; j < 8; j++) {
        const int c = cb + 8 * j;
        *reinterpret_cast<uint32_t*>(ctx + (size_t)r0g * DM + c) =
            pack2h(of[j][0] * inv0, of[j][1] * inv0);
        *reinterpret_cast<uint32_t*>(ctx + (size_t)(r0g + 8) * DM + c) =
            pack2h(of[j][2] * inv1, of[j][3] * inv1);
    }
}

// ---------------------------------------------------------------------------
// Launch
// ---------------------------------------------------------------------------
extern "C" void kernel_launch(void* const* d_in, const int* in_sizes, int n_in,
                              void* d_out, int out_size)
{
    (void)in_sizes; (void)n_in; (void)out_size;
    const float* x     = (const float*)d_in[0];
    const float* qkv_w = (const float*)d_in[1];
    const float* qkv_b = (const float*)d_in[2];
    const float* out_w = (const float*)d_in[3];
    const float* out_b = (const float*)d_in[4];
    const float* ff1_w = (const float*)d_in[5];
    const float* ff1_b = (const float*)d_in[6];
    const float* ff2_w = (const float*)d_in[7];
    const float* ff2_b = (const float*)d_in[8];
    const float* ln1_g = (const float*)d_in[9];
    const float* ln1_b = (const float*)d_in[10];
    const float* ln2_g = (const float*)d_in[11];
    const float* ln2_b = (const float*)d_in[12];
    float* out = (float*)d_out;

    __half *q, *a, *bbuf, *w1, *w2, *w3, *w4;
    cudaGetSymbolAddress((void**)&q, g_q);
    cudaGetSymbolAddress((void**)&a, g_a);
    cudaGetSymbolAddress((void**)&bbuf, g_b);
    cudaGetSymbolAddress((void**)&w1, g_w1);
    cudaGetSymbolAddress((void**)&w2, g_w2);
    cudaGetSymbolAddress((void**)&w3, g_w3);
    cudaGetSymbolAddress((void**)&w4, g_w4);

    cudaFuncSetAttribute(attn_kernel, cudaFuncAttributeMaxDynamicSharedMemorySize, AT_SMEM);
    cudaFuncSetAttribute(tgemm_kernel<1>, cudaFuncAttributeMaxDynamicSharedMemorySize, TG_SMEM);
    cudaFuncSetAttribute(tgemm_kernel<2>, cudaFuncAttributeMaxDynamicSharedMemorySize, TG_SMEM);
    cudaFuncSetAttribute(tgemm_kernel<3>, cudaFuncAttributeMaxDynamicSharedMemorySize, TG_SMEM);

    const dim3 tb(32, 8);

    // 0) weight transpose -> fp16
    wconv_kernel<<<dim3(3 * DM / 32, DM / 32),  tb>>>(qkv_w, w1, DM,  3 * DM);
    wconv_kernel<<<dim3(DM / 32,     DM / 32),  tb>>>(out_w, w2, DM,  DM);
    wconv_kernel<<<dim3(FFH / 32,    DM / 32),  tb>>>(ff1_w, w3, DM,  FFH);
    wconv_kernel<<<dim3(DM / 32,     FFH / 32), tb>>>(ff2_w, w4, FFH, DM);

    // 1) bufA = LN1(x)  (fp16)
    ln_kernel<<<NROWS, 256>>>(x, ln1_g, ln1_b, a);

    // 2) qkv(fp16, q pre-scaled) = bufA @ qkv_w + qkv_b     [8192, 3072]
    tgemm_kernel<3><<<dim3(3 * DM / 128, NROWS / 128), 256, TG_SMEM>>>(
        a, w1, qkv_b, nullptr, nullptr, q, 3 * DM, DM);

    // 3) bufB = attention(qkv)  (fp16 ctx)
    attn_kernel<<<dim3(L_SEQ / 128, BATCH * NH), 256, AT_SMEM>>>(q, bbuf);

    // 4) out = x + bufB @ out_w + out_b                     [8192, 1024]
    tgemm_kernel<2><<<dim3(DM / 128, NROWS / 128), 256, TG_SMEM>>>(
        bbuf, w2, out_b, x, out, nullptr, DM, DM);

    // 5) bufA = LN2(out)
    ln_kernel<<<NROWS, 256>>>(out, ln2_g, ln2_b, a);

    // 6) bufB = GELU(bufA @ ff1_w + ff1_b)                  [8192, 2048]
    tgemm_kernel<1><<<dim3(FFH / 128, NROWS / 128), 256, TG_SMEM>>>(
        a, w3, ff1_b, nullptr, nullptr, bbuf, FFH, DM);

    // 7) out = out + bufB @ ff2_w + ff2_b                   [8192, 1024]
    tgemm_kernel<2><<<dim3(DM / 128, NROWS / 128), 256, TG_SMEM>>>(
        bbuf, w4, ff2_b, out, out, nullptr, DM, FFH);
}

// round 14
// speedup vs baseline: 5.8364x; 1.0934x over previous
#include <cuda_runtime.h>
#include <cuda_fp16.h>
#include <math.h>
#include <stdint.h>

// ---------------------------------------------------------------------------
// Problem constants
// ---------------------------------------------------------------------------
#define DM     1024
#define L_SEQ  2048
#define BATCH  4
#define NROWS  8192
#define NH     16
#define DH     64
#define FFH    2048

// ---------------------------------------------------------------------------
// Scratch (device globals; allocation-free per harness rules)
// ---------------------------------------------------------------------------
__device__ __half g_q [(size_t)NROWS * 3 * DM];   // qkv fp16 (q pre-scaled)
__device__ __half g_a [(size_t)NROWS * FFH];      // activation buffer A
__device__ __half g_b [(size_t)NROWS * FFH];      // activation buffer B
__device__ __half g_w1[(size_t)3 * DM * DM];
__device__ __half g_w2[(size_t)DM * DM];
__device__ __half g_w3[(size_t)FFH * DM];
__device__ __half g_w4[(size_t)DM * FFH];

// ---------------------------------------------------------------------------
// PTX helpers (portable: cp.async / ldmatrix / mma.sync only)
// ---------------------------------------------------------------------------
__device__ __forceinline__ uint32_t smem_u32(const void* p) {
    uint32_t a;
    asm("{ .reg .u64 t; cvta.to.shared.u64 t, %1; cvt.u32.u64 %0, t; }" : "=r"(a) : "l"(p));
    return a;
}
__device__ __forceinline__ void cpa16(uint32_t dst, const void* src) {
    asm volatile("cp.async.cg.shared.global [%0], [%1], 16;" :: "r"(dst), "l"(src));
}
#define CP_COMMIT() asm volatile("cp.async.commit_group;" ::: "memory")
#define CP_WAIT(n)  asm volatile("cp.async.wait_group %0;" :: "n"(n) : "memory")

__device__ __forceinline__ void ldsm_x4(uint32_t addr, uint32_t& r0, uint32_t& r1,
                                        uint32_t& r2, uint32_t& r3) {
    asm volatile("ldmatrix.sync.aligned.m8n8.x4.shared.b16 {%0,%1,%2,%3}, [%4];"
                 : "=r"(r0), "=r"(r1), "=r"(r2), "=r"(r3) : "r"(addr));
}
__device__ __forceinline__ void ldsm_x4_t(uint32_t addr, uint32_t& r0, uint32_t& r1,
                                          uint32_t& r2, uint32_t& r3) {
    asm volatile("ldmatrix.sync.aligned.m8n8.x4.trans.shared.b16 {%0,%1,%2,%3}, [%4];"
                 : "=r"(r0), "=r"(r1), "=r"(r2), "=r"(r3) : "r"(addr));
}
__device__ __forceinline__ void mma16816(float* c, const uint32_t* a, const uint32_t* b) {
    asm volatile(
        "mma.sync.aligned.m16n8k16.row.col.f32.f16.f16.f32 "
        "{%0,%1,%2,%3}, {%4,%5,%6,%7}, {%8,%9}, {%0,%1,%2,%3};"
        : "+f"(c[0]), "+f"(c[1]), "+f"(c[2]), "+f"(c[3])
        : "r"(a[0]), "r"(a[1]), "r"(a[2]), "r"(a[3]), "r"(b[0]), "r"(b[1]));
}
__device__ __forceinline__ uint32_t sw128(uint32_t off) {
    return off ^ ((off >> 3) & 0x70);
}
__device__ __forceinline__ uint32_t pack2h(float a, float b) {
    __half2 H = __floats2half2_rn(a, b);
    return *reinterpret_cast<uint32_t*>(&H);
}

// ---------------------------------------------------------------------------
// Weight transpose: W[K,N] fp32 -> Wt[N,K] fp16 (K-major)
// ---------------------------------------------------------------------------
__global__ void wconv_kernel(const float* __restrict__ W,
                             __half* __restrict__ Wt, int K, int N)
{
    __shared__ float t[32][33];
    const int bx = blockIdx.x, by = blockIdx.y;
    const int tx = threadIdx.x, ty = threadIdx.y;
    #pragma unroll
    for (int j = 0; j < 4; j++)
        t[ty + j * 8][tx] = W[(size_t)(by * 32 + ty + j * 8) * N + bx * 32 + tx];
    __syncthreads();
    #pragma unroll
    for (int j = 0; j < 4; j++) {
        const float v = t[tx][ty + j * 8];
        const int n = bx * 32 + ty + j * 8, k = by * 32 + tx;
        Wt[(size_t)n * K + k] = __float2half_rn(v);
    }
}

// ---------------------------------------------------------------------------
// LayerNorm -> fp16
// ---------------------------------------------------------------------------
__global__ void ln_kernel(const float* __restrict__ x,
                          const float* __restrict__ gam,
                          const float* __restrict__ bet,
                          __half* __restrict__ o)
{
    const int row = blockIdx.x;
    const int t   = threadIdx.x;
    const float4 v = reinterpret_cast<const float4*>(x + (size_t)row * DM)[t];

    float s  = v.x + v.y + v.z + v.w;
    float ss = v.x*v.x + v.y*v.y + v.z*v.z + v.w*v.w;

    __shared__ float rs[8], rq[8];
    #pragma unroll
    for (int m = 16; m > 0; m >>= 1) {
        s  += __shfl_down_sync(0xffffffffu, s,  m);
        ss += __shfl_down_sync(0xffffffffu, ss, m);
    }
    if ((t & 31) == 0) { rs[t >> 5] = s; rq[t >> 5] = ss; }
    __syncthreads();
    if (t == 0) {
        float a = 0.f, b = 0.f;
        #pragma unroll
        for (int i = 0; i < 8; i++) { a += rs[i]; b += rq[i]; }
        rs[0] = a; rq[0] = b;
    }
    __syncthreads();

    const float mean = rs[0] * (1.0f / DM);
    const float var  = rq[0] * (1.0f / DM) - mean * mean;
    const float rstd = rsqrtf(var + 1e-5f);

    const float4 g4 = reinterpret_cast<const float4*>(gam)[t];
    const float4 b4 = reinterpret_cast<const float4*>(bet)[t];
    const float o0 = (v.x - mean) * rstd * g4.x + b4.x;
    const float o1 = (v.y - mean) * rstd * g4.y + b4.y;
    const float o2 = (v.z - mean) * rstd * g4.z + b4.z;
    const float o3 = (v.w - mean) * rstd * g4.w + b4.w;

    const size_t idx = (size_t)row * DM + t * 4;
    *reinterpret_cast<uint2*>(o + idx) = make_uint2(pack2h(o0, o1), pack2h(o2, o3));
}

// ---------------------------------------------------------------------------
// Shared tile loader: 128 rows x 64 fp16 cols, row stride 'ldg' elems, SW128.
// ---------------------------------------------------------------------------
__device__ __forceinline__ void fill_tile(uint32_t sdst, const __half* g,
                                          int row0, int k0, int ldg, int tid)
{
    #pragma unroll
    for (int i = 0; i < 4; i++) {
        const int idx = i * 256 + tid;
        const int r = idx >> 3, c = idx & 7;
        const uint32_t off = (uint32_t)(r * 128 + c * 16);
        const uint32_t so  = sdst + sw128(off);
        const char* src = (const char*)g + (((size_t)(row0 + r)) * ldg + (size_t)k0 + c * 8) * 2;
        cpa16(so, src);
    }
}

// ---------------------------------------------------------------------------
// mma.sync fp16 GEMM (single-term): C = A @ Wt^T
// 128x128 CTA tile, 8 warps (2x4), warp 64x32. K chunks of 64, 3-stage pipeline.
// EPI: 1 = +bias,GELU -> fp16 ; 2 = +bias+res -> fp32 ;
//      3 = +bias, q-cols x0.125 -> fp16 (qkv)
// ---------------------------------------------------------------------------
#define STG_A  0
#define STG_B  16384
#define STG_SZ 32768
#define TG_SMEM (3 * STG_SZ)   /* 96 KB */

template<int EPI>
__global__ __launch_bounds__(256, 1)
void tgemm_kernel(const __half* __restrict__ A, const __half* __restrict__ B,
                  const float* __restrict__ bias, const float* __restrict__ res,
                  float* __restrict__ C, __half* __restrict__ Ch,
                  int N, int K)
{
    extern __shared__ char smem[];
    const uint32_t sb = smem_u32(smem);
    const int tid  = threadIdx.x;
    const int wid  = tid >> 5, lane = tid & 31;
    const int bm   = blockIdx.y, bn = blockIdx.x;
    const int wm   = (wid >> 2) * 64;
    const int wn   = (wid & 3) * 32;

    float acc[4][4][4];
    #pragma unroll
    for (int mt = 0; mt < 4; mt++)
        #pragma unroll
        for (int nt = 0; nt < 4; nt++)
            #pragma unroll
            for (int e = 0; e < 4; e++) acc[mt][nt][e] = 0.f;

    const int nch = K >> 6;

    // prologue: stages 0, 1
    fill_tile(sb + STG_A, A, bm * 128, 0, K, tid);
    fill_tile(sb + STG_B, B, bn * 128, 0, K, tid);
    CP_COMMIT();
    if (nch > 1) {
        fill_tile(sb + STG_SZ + STG_A, A, bm * 128, 64, K, tid);
        fill_tile(sb + STG_SZ + STG_B, B, bn * 128, 64, K, tid);
        CP_COMMIT();
    }

    int slot = 0;
    for (int ch = 0; ch < nch; ++ch) {
        if (ch + 2 < nch) {
            int ns = slot + 2;                 // (slot + 2) mod 3
            if (ns >= 3) ns -= 3;
            const uint32_t nst = sb + ns * STG_SZ;
            const int k1 = (ch + 2) << 6;
            fill_tile(nst + STG_A, A, bm * 128, k1, K, tid);
            fill_tile(nst + STG_B, B, bn * 128, k1, K, tid);
            CP_COMMIT();
            CP_WAIT(2);
        } else if (ch + 1 < nch) {
            CP_WAIT(1);
        } else {
            CP_WAIT(0);
        }
        __syncthreads();

        const uint32_t st = sb + slot * STG_SZ;
        #pragma unroll
        for (int ks = 0; ks < 4; ks++) {
            const uint32_t kb = (uint32_t)(ks * 32 + ((lane >> 4) << 4));
            uint32_t af[4][4], bf[4][2];
            #pragma unroll
            for (int mt = 0; mt < 4; mt++) {
                const uint32_t off = (uint32_t)((wm + mt * 16 + (lane & 15)) * 128) + kb;
                const uint32_t so  = sw128(off);
                ldsm_x4(st + STG_A + so, af[mt][0], af[mt][1], af[mt][2], af[mt][3]);
            }
            #pragma unroll
            for (int np = 0; np < 2; np++) {
                const uint32_t off = (uint32_t)((wn + np * 16 + (lane & 15)) * 128) + kb;
                const uint32_t so  = sw128(off);
                uint32_t r0, r1, r2, r3;
                ldsm_x4(st + STG_B + so, r0, r1, r2, r3);
                bf[np * 2][0] = r0; bf[np * 2 + 1][0] = r1;
                bf[np * 2][1] = r2; bf[np * 2 + 1][1] = r3;
            }
            #pragma unroll
            for (int mt = 0; mt < 4; mt++)
                #pragma unroll
                for (int nt = 0; nt < 4; nt++)
                    mma16816(acc[mt][nt], af[mt], bf[nt]);
        }
        __syncthreads();
        slot = (slot + 1 == 3) ? 0 : slot + 1;
    }

    const int rbase = bm * 128 + wm + (lane >> 2);
    const int cbase = bn * 128 + wn + (lane & 3) * 2;
    #pragma unroll
    for (int mt = 0; mt < 4; mt++) {
        #pragma unroll
        for (int half = 0; half < 2; half++) {
            const int r = rbase + mt * 16 + half * 8;
            const size_t rowoff = (size_t)r * N;
            #pragma unroll
            for (int nt = 0; nt < 4; nt++) {
                const int c = cbase + nt * 8;
                float v0 = acc[mt][nt][half * 2 + 0] + __ldg(bias + c);
                float v1 = acc[mt][nt][half * 2 + 1] + __ldg(bias + c + 1);
                if (EPI == 2) {
                    const float2 rv = *reinterpret_cast<const float2*>(res + rowoff + c);
                    v0 += rv.x; v1 += rv.y;
                    *reinterpret_cast<float2*>(C + rowoff + c) = make_float2(v0, v1);
                } else if (EPI == 1) {
                    v0 = 0.5f * v0 * (1.0f + erff(v0 * 0.70710678118654752f));
                    v1 = 0.5f * v1 * (1.0f + erff(v1 * 0.70710678118654752f));
                    *reinterpret_cast<uint32_t*>(Ch + rowoff + c) = pack2h(v0, v1);
                } else {  // EPI == 3
                    const float sc = (c < DM) ? 0.125f : 1.0f;  // q-scale, exact
                    *reinterpret_cast<uint32_t*>(Ch + rowoff + c) = pack2h(v0 * sc, v1 * sc);
                }
            }
        }
    }
}

// ---------------------------------------------------------------------------
// Tensor-core flash attention, fp16 (S 1-term, P@V 1-term fp16 P).
// CTA = 128 q-rows x (b,h); 8 warps x 16 rows. KV tiles of 128, double-buffered.
// ---------------------------------------------------------------------------
#define AT_Q    0
#define AT_STG  16384
#define AT_K    0
#define AT_V    16384
#define AT_STG_SZ 32768
#define AT_SMEM (AT_STG + 2 * AT_STG_SZ)   /* 80 KB */

__global__ __launch_bounds__(256, 1)
void attn_kernel(const __half* __restrict__ qkv, __half* __restrict__ ctx)
{
    extern __shared__ char smem[];
    const uint32_t sb = smem_u32(smem);
    const int tid  = threadIdx.x;
    const int wid  = tid >> 5, lane = tid & 31;
    const int b    = blockIdx.y >> 4, h = blockIdx.y & 15;
    const int q0   = blockIdx.x * 128;
    const int wm   = wid * 16;

    const int qcol = h * DH;
    const int kcol = DM + h * DH;
    const int vcol = 2 * DM + h * DH;
    const int rowQ = b * L_SEQ + q0;
    const int rowB = b * L_SEQ;

    fill_tile(sb + AT_Q, qkv, rowQ, qcol, 3 * DM, tid);
    fill_tile(sb + AT_STG + AT_K, qkv, rowB, kcol, 3 * DM, tid);
    fill_tile(sb + AT_STG + AT_V, qkv, rowB, vcol, 3 * DM, tid);
    CP_COMMIT();

    uint32_t qf[4][4];
    float m0 = -3.0e38f, m1 = -3.0e38f, l0 = 0.f, l1 = 0.f;
    float of[8][4];
    #pragma unroll
    for (int j = 0; j < 8; j++)
        #pragma unroll
        for (int e = 0; e < 4; e++) of[j][e] = 0.f;

    for (int t = 0; t < L_SEQ / 128; t++) {
        if (t + 1 < L_SEQ / 128) {
            const uint32_t nst = sb + AT_STG + ((t + 1) & 1) * AT_STG_SZ;
            const int rk = rowB + (t + 1) * 128;
            fill_tile(nst + AT_K, qkv, rk, kcol, 3 * DM, tid);
            fill_tile(nst + AT_V, qkv, rk, vcol, 3 * DM, tid);
            CP_COMMIT();
            CP_WAIT(1);
        } else {
            CP_WAIT(0);
        }
        __syncthreads();

        if (t == 0) {
            #pragma unroll
            for (int kb = 0; kb < 4; kb++) {
                const uint32_t off = (uint32_t)((wm + (lane & 15)) * 128 + kb * 32
                                               + ((lane >> 4) << 4));
                const uint32_t so = sw128(off);
                ldsm_x4(sb + AT_Q + so, qf[kb][0], qf[kb][1], qf[kb][2], qf[kb][3]);
            }
        }

        const uint32_t st = sb + AT_STG + (t & 1) * AT_STG_SZ;

        // ---- S = Q @ K^T (single term) ----
        float sf[16][4];
        #pragma unroll
        for (int j = 0; j < 16; j++)
            #pragma unroll
            for (int e = 0; e < 4; e++) sf[j][e] = 0.f;

        #pragma unroll
        for (int kb = 0; kb < 4; kb++)
            #pragma unroll
            for (int np = 0; np < 8; np++) {
                const uint32_t off = (uint32_t)((np * 16 + (lane & 15)) * 128 + kb * 32
                                               + ((lane >> 4) << 4));
                const uint32_t so = sw128(off);
                uint32_t r0, r1, r2, r3;
                ldsm_x4(st + AT_K + so, r0, r1, r2, r3);
                uint32_t k0[2] = {r0, r2}, k1[2] = {r1, r3};
                mma16816(sf[2 * np],     qf[kb], k0);
                mma16816(sf[2 * np + 1], qf[kb], k1);
            }

        // ---- online softmax on fragments ----
        float mt0 = -3.0e38f, mt1 = -3.0e38f;
        #pragma unroll
        for (int j = 0; j < 16; j++) {
            mt0 = fmaxf(mt0, fmaxf(sf[j][0], sf[j][1]));
            mt1 = fmaxf(mt1, fmaxf(sf[j][2], sf[j][3]));
        }
        mt0 = fmaxf(mt0, __shfl_xor_sync(0xffffffffu, mt0, 1));
        mt0 = fmaxf(mt0, __shfl_xor_sync(0xffffffffu, mt0, 2));
        mt1 = fmaxf(mt1, __shfl_xor_sync(0xffffffffu, mt1, 1));
        mt1 = fmaxf(mt1, __shfl_xor_sync(0xffffffffu, mt1, 2));

        const float mn0 = fmaxf(m0, mt0), mn1 = fmaxf(m1, mt1);
        const float cr0 = __expf(m0 - mn0), cr1 = __expf(m1 - mn1);
        m0 = mn0; m1 = mn1;

        float rs0 = 0.f, rs1 = 0.f;
        #pragma unroll
        for (int j = 0; j < 16; j++) {
            sf[j][0] = __expf(sf[j][0] - mn0);
            sf[j][1] = __expf(sf[j][1] - mn0);
            sf[j][2] = __expf(sf[j][2] - mn1);
            sf[j][3] = __expf(sf[j][3] - mn1);
            rs0 += sf[j][0] + sf[j][1];
            rs1 += sf[j][2] + sf[j][3];
        }
        rs0 += __shfl_xor_sync(0xffffffffu, rs0, 1);
        rs0 += __shfl_xor_sync(0xffffffffu, rs0, 2);
        rs1 += __shfl_xor_sync(0xffffffffu, rs1, 1);
        rs1 += __shfl_xor_sync(0xffffffffu, rs1, 2);
        l0 = l0 * cr0 + rs0;
        l1 = l1 * cr1 + rs1;
        #pragma unroll
        for (int j = 0; j < 8; j++) {
            of[j][0] *= cr0; of[j][1] *= cr0;
            of[j][2] *= cr1; of[j][3] *= cr1;
        }

        // ---- O += P @ V (single-term fp16 P) ----
        #pragma unroll
        for (int kb2 = 0; kb2 < 8; kb2++) {
            uint32_t ph[4];
            ph[0] = pack2h(sf[2 * kb2][0],     sf[2 * kb2][1]);
            ph[1] = pack2h(sf[2 * kb2][2],     sf[2 * kb2][3]);
            ph[2] = pack2h(sf[2 * kb2 + 1][0], sf[2 * kb2 + 1][1]);
            ph[3] = pack2h(sf[2 * kb2 + 1][2], sf[2 * kb2 + 1][3]);
            #pragma unroll
            for (int dp = 0; dp < 4; dp++) {
                const uint32_t off = (uint32_t)((kb2 * 16 + ((lane >> 3) & 1) * 8 + (lane & 7)) * 128
                                               + (dp * 16 + (lane >> 4) * 8) * 2);
                const uint32_t so = sw128(off);
                uint32_t r0, r1, r2, r3;
                ldsm_x4_t(st + AT_V + so, r0, r1, r2, r3);
                uint32_t v0[2] = {r0, r1}, v1[2] = {r2, r3};
                mma16816(of[dp * 2],     ph, v0);
                mma16816(of[dp * 2 + 1], ph, v1);
            }
        }
        __syncthreads();
    }

    // ---- normalize + write ctx fp16 ----
    const float inv0 = 1.0f / l0, inv1 = 1.0f / l1;
    const int r0g = b * L_SEQ + q0 + wm + (lane >> 2);
    const int cb  = h * DH + 2 * (lane & 3);
    #pragma unroll
    for (int j = 0; j < 8; j++) {
        const int c = cb + 8 * j;
        *reinterpret_cast<uint32_t*>(ctx + (size_t)r0g * DM + c) =
            pack2h(of[j][0] * inv0, of[j][1] * inv0);
        *reinterpret_cast<uint32_t*>(ctx + (size_t)(r0g + 8) * DM + c) =
            pack2h(of[j][2] * inv1, of[j][3] * inv1);
    }
}

// ---------------------------------------------------------------------------
// Launch
// ---------------------------------------------------------------------------
extern "C" void kernel_launch(void* const* d_in, const int* in_sizes, int n_in,
                              void* d_out, int out_size)
{
    (void)in_sizes; (void)n_in; (void)out_size;
    const float* x     = (const float*)d_in[0];
    const float* qkv_w = (const float*)d_in[1];
    const float* qkv_b = (const float*)d_in[2];
    const float* out_w = (const float*)d_in[3];
    const float* out_b = (const float*)d_in[4];
    const float* ff1_w = (const float*)d_in[5];
    const float* ff1_b = (const float*)d_in[6];
    const float* ff2_w = (const float*)d_in[7];
    const float* ff2_b = (const float*)d_in[8];
    const float* ln1_g = (const float*)d_in[9];
    const float* ln1_b = (const float*)d_in[10];
    const float* ln2_g = (const float*)d_in[11];
    const float* ln2_b = (const float*)d_in[12];
    float* out = (float*)d_out;

    __half *q, *a, *bbuf, *w1, *w2, *w3, *w4;
    cudaGetSymbolAddress((void**)&q, g_q);
    cudaGetSymbolAddress((void**)&a, g_a);
    cudaGetSymbolAddress((void**)&bbuf, g_b);
    cudaGetSymbolAddress((void**)&w1, g_w1);
    cudaGetSymbolAddress((void**)&w2, g_w2);
    cudaGetSymbolAddress((void**)&w3, g_w3);
    cudaGetSymbolAddress((void**)&w4, g_w4);

    cudaFuncSetAttribute(attn_kernel, cudaFuncAttributeMaxDynamicSharedMemorySize, AT_SMEM);
    cudaFuncSetAttribute(tgemm_kernel<1>, cudaFuncAttributeMaxDynamicSharedMemorySize, TG_SMEM);
    cudaFuncSetAttribute(tgemm_kernel<2>, cudaFuncAttributeMaxDynamicSharedMemorySize, TG_SMEM);
    cudaFuncSetAttribute(tgemm_kernel<3>, cudaFuncAttributeMaxDynamicSharedMemorySize, TG_SMEM);

    const dim3 tb(32, 8);

    // 0) weight transpose -> fp16
    wconv_kernel<<<dim3(3 * DM / 32, DM / 32),  tb>>>(qkv_w, w1, DM,  3 * DM);
    wconv_kernel<<<dim3(DM / 32,     DM / 32),  tb>>>(out_w, w2, DM,  DM);
    wconv_kernel<<<dim3(FFH / 32,    DM / 32),  tb>>>(ff1_w, w3, DM,  FFH);
    wconv_kernel<<<dim3(DM / 32,     FFH / 32), tb>>>(ff2_w, w4, FFH, DM);

    // 1) bufA = LN1(x)  (fp16)
    ln_kernel<<<NROWS, 256>>>(x, ln1_g, ln1_b, a);

    // 2) qkv(fp16, q pre-scaled) = bufA @ qkv_w + qkv_b     [8192, 3072]
    tgemm_kernel<3><<<dim3(3 * DM / 128, NROWS / 128), 256, TG_SMEM>>>(
        a, w1, qkv_b, nullptr, nullptr, q, 3 * DM, DM);

    // 3) bufB = attention(qkv)  (fp16 ctx)
    attn_kernel<<<dim3(L_SEQ / 128, BATCH * NH), 256, AT_SMEM>>>(q, bbuf);

    // 4) out = x + bufB @ out_w + out_b                     [8192, 1024]
    tgemm_kernel<2><<<dim3(DM / 128, NROWS / 128), 256, TG_SMEM>>>(
        bbuf, w2, out_b, x, out, nullptr, DM, DM);

    // 5) bufA = LN2(out)
    ln_kernel<<<NROWS, 256>>>(out, ln2_g, ln2_b, a);

    // 6) bufB = GELU(bufA @ ff1_w + ff1_b)                  [8192, 2048]
    tgemm_kernel<1><<<dim3(FFH / 128, NROWS / 128), 256, TG_SMEM>>>(
        a, w3, ff1_b, nullptr, nullptr, bbuf, FFH, DM);

    // 7) out = out + bufB @ ff2_w + ff2_b                   [8192, 1024]
    tgemm_kernel<2><<<dim3(DM / 128, NROWS / 128), 256, TG_SMEM>>>(
        bbuf, w4, ff2_b, out, out, nullptr, DM, FFH);
}

// round 15
// speedup vs baseline: 6.2779x; 1.0756x over previous
#include <cuda_runtime.h>
#include <cuda_fp16.h>
#include <math.h>
#include <stdint.h>

// ---------------------------------------------------------------------------
// Problem constants
// ---------------------------------------------------------------------------
#define DM     1024
#define L_SEQ  2048
#define BATCH  4
#define NROWS  8192
#define NH     16
#define DH     64
#define FFH    2048

// ---------------------------------------------------------------------------
// Scratch (device globals; allocation-free per harness rules)
// ---------------------------------------------------------------------------
__device__ __half g_q [(size_t)NROWS * 3 * DM];   // qkv fp16 (q pre-scaled)
__device__ __half g_a [(size_t)NROWS * FFH];      // activation buffer A
__device__ __half g_b [(size_t)NROWS * FFH];      // activation buffer B
__device__ __half g_w1[(size_t)3 * DM * DM];
__device__ __half g_w2[(size_t)DM * DM];
__device__ __half g_w3[(size_t)FFH * DM];
__device__ __half g_w4[(size_t)DM * FFH];

// ---------------------------------------------------------------------------
// PTX helpers (portable: cp.async / ldmatrix / mma.sync only)
// ---------------------------------------------------------------------------
__device__ __forceinline__ uint32_t smem_u32(const void* p) {
    uint32_t a;
    asm("{ .reg .u64 t; cvta.to.shared.u64 t, %1; cvt.u32.u64 %0, t; }" : "=r"(a) : "l"(p));
    return a;
}
__device__ __forceinline__ void cpa16(uint32_t dst, const void* src) {
    asm volatile("cp.async.cg.shared.global [%0], [%1], 16;" :: "r"(dst), "l"(src));
}
#define CP_COMMIT() asm volatile("cp.async.commit_group;" ::: "memory")
#define CP_WAIT(n)  asm volatile("cp.async.wait_group %0;" :: "n"(n) : "memory")

__device__ __forceinline__ void ldsm_x4(uint32_t addr, uint32_t& r0, uint32_t& r1,
                                        uint32_t& r2, uint32_t& r3) {
    asm volatile("ldmatrix.sync.aligned.m8n8.x4.shared.b16 {%0,%1,%2,%3}, [%4];"
                 : "=r"(r0), "=r"(r1), "=r"(r2), "=r"(r3) : "r"(addr));
}
__device__ __forceinline__ void ldsm_x4_t(uint32_t addr, uint32_t& r0, uint32_t& r1,
                                          uint32_t& r2, uint32_t& r3) {
    asm volatile("ldmatrix.sync.aligned.m8n8.x4.trans.shared.b16 {%0,%1,%2,%3}, [%4];"
                 : "=r"(r0), "=r"(r1), "=r"(r2), "=r"(r3) : "r"(addr));
}
__device__ __forceinline__ void mma16816(float* c, const uint32_t* a, const uint32_t* b) {
    asm volatile(
        "mma.sync.aligned.m16n8k16.row.col.f32.f16.f16.f32 "
        "{%0,%1,%2,%3}, {%4,%5,%6,%7}, {%8,%9}, {%0,%1,%2,%3};"
        : "+f"(c[0]), "+f"(c[1]), "+f"(c[2]), "+f"(c[3])
        : "r"(a[0]), "r"(a[1]), "r"(a[2]), "r"(a[3]), "r"(b[0]), "r"(b[1]));
}
__device__ __forceinline__ uint32_t sw128(uint32_t off) {
    return off ^ ((off >> 3) & 0x70);
}
__device__ __forceinline__ uint32_t pack2h(float a, float b) {
    __half2 H = __floats2half2_rn(a, b);
    return *reinterpret_cast<uint32_t*>(&H);
}

// ---------------------------------------------------------------------------
// Weight transpose: W[K,N] fp32 -> Wt[N,K] fp16 (K-major)
// ---------------------------------------------------------------------------
__global__ void wconv_kernel(const float* __restrict__ W,
                             __half* __restrict__ Wt, int K, int N)
{
    __shared__ float t[32][33];
    const int bx = blockIdx.x, by = blockIdx.y;
    const int tx = threadIdx.x, ty = threadIdx.y;
    #pragma unroll
    for (int j = 0; j < 4; j++)
        t[ty + j * 8][tx] = W[(size_t)(by * 32 + ty + j * 8) * N + bx * 32 + tx];
    __syncthreads();
    #pragma unroll
    for (int j = 0; j < 4; j++) {
        const float v = t[tx][ty + j * 8];
        const int n = bx * 32 + ty + j * 8, k = by * 32 + tx;
        Wt[(size_t)n * K + k] = __float2half_rn(v);
    }
}

// ---------------------------------------------------------------------------
// LayerNorm -> fp16
// ---------------------------------------------------------------------------
__global__ void ln_kernel(const float* __restrict__ x,
                          const float* __restrict__ gam,
                          const float* __restrict__ bet,
                          __half* __restrict__ o)
{
    const int row = blockIdx.x;
    const int t   = threadIdx.x;
    const float4 v = reinterpret_cast<const float4*>(x + (size_t)row * DM)[t];

    float s  = v.x + v.y + v.z + v.w;
    float ss = v.x*v.x + v.y*v.y + v.z*v.z + v.w*v.w;

    __shared__ float rs[8], rq[8];
    #pragma unroll
    for (int m = 16; m > 0; m >>= 1) {
        s  += __shfl_down_sync(0xffffffffu, s,  m);
        ss += __shfl_down_sync(0xffffffffu, ss, m);
    }
    if ((t & 31) == 0) { rs[t >> 5] = s; rq[t >> 5] = ss; }
    __syncthreads();
    if (t == 0) {
        float a = 0.f, b = 0.f;
        #pragma unroll
        for (int i = 0; i < 8; i++) { a += rs[i]; b += rq[i]; }
        rs[0] = a; rq[0] = b;
    }
    __syncthreads();

    const float mean = rs[0] * (1.0f / DM);
    const float var  = rq[0] * (1.0f / DM) - mean * mean;
    const float rstd = rsqrtf(var + 1e-5f);

    const float4 g4 = reinterpret_cast<const float4*>(gam)[t];
    const float4 b4 = reinterpret_cast<const float4*>(bet)[t];
    const float o0 = (v.x - mean) * rstd * g4.x + b4.x;
    const float o1 = (v.y - mean) * rstd * g4.y + b4.y;
    const float o2 = (v.z - mean) * rstd * g4.z + b4.z;
    const float o3 = (v.w - mean) * rstd * g4.w + b4.w;

    const size_t idx = (size_t)row * DM + t * 4;
    *reinterpret_cast<uint2*>(o + idx) = make_uint2(pack2h(o0, o1), pack2h(o2, o3));
}

// ---------------------------------------------------------------------------
// Shared tile loader: 128 rows x 64 fp16 cols, row stride 'ldg' elems, SW128.
// ---------------------------------------------------------------------------
__device__ __forceinline__ void fill_tile(uint32_t sdst, const __half* g,
                                          int row0, int k0, int ldg, int tid)
{
    #pragma unroll
    for (int i = 0; i < 4; i++) {
        const int idx = i * 256 + tid;
        const int r = idx >> 3, c = idx & 7;
        const uint32_t off = (uint32_t)(r * 128 + c * 16);
        const uint32_t so  = sdst + sw128(off);
        const char* src = (const char*)g + (((size_t)(row0 + r)) * ldg + (size_t)k0 + c * 8) * 2;
        cpa16(so, src);
    }
}

// ---------------------------------------------------------------------------
// mma.sync fp16 GEMM (single-term): C = A @ Wt^T
// 128x128 CTA tile, 8 warps (2x4), warp 64x32. K chunks of 64, 3-stage pipeline.
// __launch_bounds__(256, 2): 2 CTAs/SM (192 KB smem, <=128 regs) to hide
// per-chunk barrier + ldsm latency that occ-1 left exposed.
// EPI: 1 = +bias,GELU -> fp16 ; 2 = +bias+res -> fp32 ;
//      3 = +bias, q-cols x0.125 -> fp16 (qkv)
// ---------------------------------------------------------------------------
#define STG_A  0
#define STG_B  16384
#define STG_SZ 32768
#define TG_SMEM (3 * STG_SZ)   /* 96 KB */

template<int EPI>
__global__ __launch_bounds__(256, 2)
void tgemm_kernel(const __half* __restrict__ A, const __half* __restrict__ B,
                  const float* __restrict__ bias, const float* __restrict__ res,
                  float* __restrict__ C, __half* __restrict__ Ch,
                  int N, int K)
{
    extern __shared__ char smem[];
    const uint32_t sb = smem_u32(smem);
    const int tid  = threadIdx.x;
    const int wid  = tid >> 5, lane = tid & 31;
    const int bm   = blockIdx.y, bn = blockIdx.x;
    const int wm   = (wid >> 2) * 64;
    const int wn   = (wid & 3) * 32;

    float acc[4][4][4];
    #pragma unroll
    for (int mt = 0; mt < 4; mt++)
        #pragma unroll
        for (int nt = 0; nt < 4; nt++)
            #pragma unroll
            for (int e = 0; e < 4; e++) acc[mt][nt][e] = 0.f;

    const int nch = K >> 6;

    // prologue: stages 0, 1
    fill_tile(sb + STG_A, A, bm * 128, 0, K, tid);
    fill_tile(sb + STG_B, B, bn * 128, 0, K, tid);
    CP_COMMIT();
    if (nch > 1) {
        fill_tile(sb + STG_SZ + STG_A, A, bm * 128, 64, K, tid);
        fill_tile(sb + STG_SZ + STG_B, B, bn * 128, 64, K, tid);
        CP_COMMIT();
    }

    int slot = 0;
    for (int ch = 0; ch < nch; ++ch) {
        if (ch + 2 < nch) {
            int ns = slot + 2;                 // (slot + 2) mod 3
            if (ns >= 3) ns -= 3;
            const uint32_t nst = sb + ns * STG_SZ;
            const int k1 = (ch + 2) << 6;
            fill_tile(nst + STG_A, A, bm * 128, k1, K, tid);
            fill_tile(nst + STG_B, B, bn * 128, k1, K, tid);
            CP_COMMIT();
            CP_WAIT(2);
        } else if (ch + 1 < nch) {
            CP_WAIT(1);
        } else {
            CP_WAIT(0);
        }
        __syncthreads();

        const uint32_t st = sb + slot * STG_SZ;
        #pragma unroll
        for (int ks = 0; ks < 4; ks++) {
            const uint32_t kb = (uint32_t)(ks * 32 + ((lane >> 4) << 4));
            uint32_t af[4][4], bf[4][2];
            #pragma unroll
            for (int mt = 0; mt < 4; mt++) {
                const uint32_t off = (uint32_t)((wm + mt * 16 + (lane & 15)) * 128) + kb;
                const uint32_t so  = sw128(off);
                ldsm_x4(st + STG_A + so, af[mt][0], af[mt][1], af[mt][2], af[mt][3]);
            }
            #pragma unroll
            for (int np = 0; np < 2; np++) {
                const uint32_t off = (uint32_t)((wn + np * 16 + (lane & 15)) * 128) + kb;
                const uint32_t so  = sw128(off);
                uint32_t r0, r1, r2, r3;
                ldsm_x4(st + STG_B + so, r0, r1, r2, r3);
                bf[np * 2][0] = r0; bf[np * 2 + 1][0] = r1;
                bf[np * 2][1] = r2; bf[np * 2 + 1][1] = r3;
            }
            #pragma unroll
            for (int mt = 0; mt < 4; mt++)
                #pragma unroll
                for (int nt = 0; nt < 4; nt++)
                    mma16816(acc[mt][nt], af[mt], bf[nt]);
        }
        __syncthreads();
        slot = (slot + 1 == 3) ? 0 : slot + 1;
    }

    const int rbase = bm * 128 + wm + (lane >> 2);
    const int cbase = bn * 128 + wn + (lane & 3) * 2;
    #pragma unroll
    for (int mt = 0; mt < 4; mt++) {
        #pragma unroll
        for (int half = 0; half < 2; half++) {
            const int r = rbase + mt * 16 + half * 8;
            const size_t rowoff = (size_t)r * N;
            #pragma unroll
            for (int nt = 0; nt < 4; nt++) {
                const int c = cbase + nt * 8;
                float v0 = acc[mt][nt][half * 2 + 0] + __ldg(bias + c);
                float v1 = acc[mt][nt][half * 2 + 1] + __ldg(bias + c + 1);
                if (EPI == 2) {
                    const float2 rv = *reinterpret_cast<const float2*>(res + rowoff + c);
                    v0 += rv.x; v1 += rv.y;
                    *reinterpret_cast<float2*>(C + rowoff + c) = make_float2(v0, v1);
                } else if (EPI == 1) {
                    v0 = 0.5f * v0 * (1.0f + erff(v0 * 0.70710678118654752f));
                    v1 = 0.5f * v1 * (1.0f + erff(v1 * 0.70710678118654752f));
                    *reinterpret_cast<uint32_t*>(Ch + rowoff + c) = pack2h(v0, v1);
                } else {  // EPI == 3
                    const float sc = (c < DM) ? 0.125f : 1.0f;  // q-scale, exact
                    *reinterpret_cast<uint32_t*>(Ch + rowoff + c) = pack2h(v0 * sc, v1 * sc);
                }
            }
        }
    }
}

// ---------------------------------------------------------------------------
// Tensor-core flash attention, fp16 (S 1-term, P@V 1-term fp16 P).
// CTA = 128 q-rows x (b,h); 8 warps x 16 rows. KV tiles of 128, double-buffered.
// ---------------------------------------------------------------------------
#define AT_Q    0
#define AT_STG  16384
#define AT_K    0
#define AT_V    16384
#define AT_STG_SZ 32768
#define AT_SMEM (AT_STG + 2 * AT_STG_SZ)   /* 80 KB */

__global__ __launch_bounds__(256, 1)
void attn_kernel(const __half* __restrict__ qkv, __half* __restrict__ ctx)
{
    extern __shared__ char smem[];
    const uint32_t sb = smem_u32(smem);
    const int tid  = threadIdx.x;
    const int wid  = tid >> 5, lane = tid & 31;
    const int b    = blockIdx.y >> 4, h = blockIdx.y & 15;
    const int q0   = blockIdx.x * 128;
    const int wm   = wid * 16;

    const int qcol = h * DH;
    const int kcol = DM + h * DH;
    const int vcol = 2 * DM + h * DH;
    const int rowQ = b * L_SEQ + q0;
    const int rowB = b * L_SEQ;

    fill_tile(sb + AT_Q, qkv, rowQ, qcol, 3 * DM, tid);
    fill_tile(sb + AT_STG + AT_K, qkv, rowB, kcol, 3 * DM, tid);
    fill_tile(sb + AT_STG + AT_V, qkv, rowB, vcol, 3 * DM, tid);
    CP_COMMIT();

    uint32_t qf[4][4];
    float m0 = -3.0e38f, m1 = -3.0e38f, l0 = 0.f, l1 = 0.f;
    float of[8][4];
    #pragma unroll
    for (int j = 0; j < 8; j++)
        #pragma unroll
        for (int e = 0; e < 4; e++) of[j][e] = 0.f;

    for (int t = 0; t < L_SEQ / 128; t++) {
        if (t + 1 < L_SEQ / 128) {
            const uint32_t nst = sb + AT_STG + ((t + 1) & 1) * AT_STG_SZ;
            const int rk = rowB + (t + 1) * 128;
            fill_tile(nst + AT_K, qkv, rk, kcol, 3 * DM, tid);
            fill_tile(nst + AT_V, qkv, rk, vcol, 3 * DM, tid);
            CP_COMMIT();
            CP_WAIT(1);
        } else {
            CP_WAIT(0);
        }
        __syncthreads();

        if (t == 0) {
            #pragma unroll
            for (int kb = 0; kb < 4; kb++) {
                const uint32_t off = (uint32_t)((wm + (lane & 15)) * 128 + kb * 32
                                               + ((lane >> 4) << 4));
                const uint32_t so = sw128(off);
                ldsm_x4(sb + AT_Q + so, qf[kb][0], qf[kb][1], qf[kb][2], qf[kb][3]);
            }
        }

        const uint32_t st = sb + AT_STG + (t & 1) * AT_STG_SZ;

        // ---- S = Q @ K^T (single term) ----
        float sf[16][4];
        #pragma unroll
        for (int j = 0; j < 16; j++)
            #pragma unroll
            for (int e = 0; e < 4; e++) sf[j][e] = 0.f;

        #pragma unroll
        for (int kb = 0; kb < 4; kb++)
            #pragma unroll
            for (int np = 0; np < 8; np++) {
                const uint32_t off = (uint32_t)((np * 16 + (lane & 15)) * 128 + kb * 32
                                               + ((lane >> 4) << 4));
                const uint32_t so = sw128(off);
                uint32_t r0, r1, r2, r3;
                ldsm_x4(st + AT_K + so, r0, r1, r2, r3);
                uint32_t k0[2] = {r0, r2}, k1[2] = {r1, r3};
                mma16816(sf[2 * np],     qf[kb], k0);
                mma16816(sf[2 * np + 1], qf[kb], k1);
            }

        // ---- online softmax on fragments ----
        float mt0 = -3.0e38f, mt1 = -3.0e38f;
        #pragma unroll
        for (int j = 0; j < 16; j++) {
            mt0 = fmaxf(mt0, fmaxf(sf[j][0], sf[j][1]));
            mt1 = fmaxf(mt1, fmaxf(sf[j][2], sf[j][3]));
        }
        mt0 = fmaxf(mt0, __shfl_xor_sync(0xffffffffu, mt0, 1));
        mt0 = fmaxf(mt0, __shfl_xor_sync(0xffffffffu, mt0, 2));
        mt1 = fmaxf(mt1, __shfl_xor_sync(0xffffffffu, mt1, 1));
        mt1 = fmaxf(mt1, __shfl_xor_sync(0xffffffffu, mt1, 2));

        const float mn0 = fmaxf(m0, mt0), mn1 = fmaxf(m1, mt1);
        const float cr0 = __expf(m0 - mn0), cr1 = __expf(m1 - mn1);
        m0 = mn0; m1 = mn1;

        float rs0 = 0.f, rs1 = 0.f;
        #pragma unroll
        for (int j = 0; j < 16; j++) {
            sf[j][0] = __expf(sf[j][0] - mn0);
            sf[j][1] = __expf(sf[j][1] - mn0);
            sf[j][2] = __expf(sf[j][2] - mn1);
            sf[j][3] = __expf(sf[j][3] - mn1);
            rs0 += sf[j][0] + sf[j][1];
            rs1 += sf[j][2] + sf[j][3];
        }
        rs0 += __shfl_xor_sync(0xffffffffu, rs0, 1);
        rs0 += __shfl_xor_sync(0xffffffffu, rs0, 2);
        rs1 += __shfl_xor_sync(0xffffffffu, rs1, 1);
        rs1 += __shfl_xor_sync(0xffffffffu, rs1, 2);
        l0 = l0 * cr0 + rs0;
        l1 = l1 * cr1 + rs1;
        #pragma unroll
        for (int j = 0; j < 8; j++) {
            of[j][0] *= cr0; of[j][1] *= cr0;
            of[j][2] *= cr1; of[j][3] *= cr1;
        }

        // ---- O += P @ V (single-term fp16 P) ----
        #pragma unroll
        for (int kb2 = 0; kb2 < 8; kb2++) {
            uint32_t ph[4];
            ph[0] = pack2h(sf[2 * kb2][0],     sf[2 * kb2][1]);
            ph[1] = pack2h(sf[2 * kb2][2],     sf[2 * kb2][3]);
            ph[2] = pack2h(sf[2 * kb2 + 1][0], sf[2 * kb2 + 1][1]);
            ph[3] = pack2h(sf[2 * kb2 + 1][2], sf[2 * kb2 + 1][3]);
            #pragma unroll
            for (int dp = 0; dp < 4; dp++) {
                const uint32_t off = (uint32_t)((kb2 * 16 + ((lane >> 3) & 1) * 8 + (lane & 7)) * 128
                                               + (dp * 16 + (lane >> 4) * 8) * 2);
                const uint32_t so = sw128(off);
                uint32_t r0, r1, r2, r3;
                ldsm_x4_t(st + AT_V + so, r0, r1, r2, r3);
                uint32_t v0[2] = {r0, r1}, v1[2] = {r2, r3};
                mma16816(of[dp * 2],     ph, v0);
                mma16816(of[dp * 2 + 1], ph, v1);
            }
        }
        __syncthreads();
    }

    // ---- normalize + write ctx fp16 ----
    const float inv0 = 1.0f / l0, inv1 = 1.0f / l1;
    const int r0g = b * L_SEQ + q0 + wm + (lane >> 2);
    const int cb  = h * DH + 2 * (lane & 3);
    #pragma unroll
    for (int j = 0; j < 8; j++) {
        const int c = cb + 8 * j;
        *reinterpret_cast<uint32_t*>(ctx + (size_t)r0g * DM + c) =
            pack2h(of[j][0] * inv0, of[j][1] * inv0);
        *reinterpret_cast<uint32_t*>(ctx + (size_t)(r0g + 8) * DM + c) =
            pack2h(of[j][2] * inv1, of[j][3] * inv1);
    }
}

// ---------------------------------------------------------------------------
// Launch
// ---------------------------------------------------------------------------
extern "C" void kernel_launch(void* const* d_in, const int* in_sizes, int n_in,
                              void* d_out, int out_size)
{
    (void)in_sizes; (void)n_in; (void)out_size;
    const float* x     = (const float*)d_in[0];
    const float* qkv_w = (const float*)d_in[1];
    const float* qkv_b = (const float*)d_in[2];
    const float* out_w = (const float*)d_in[3];
    const float* out_b = (const float*)d_in[4];
    const float* ff1_w = (const float*)d_in[5];
    const float* ff1_b = (const float*)d_in[6];
    const float* ff2_w = (const float*)d_in[7];
    const float* ff2_b = (const float*)d_in[8];
    const float* ln1_g = (const float*)d_in[9];
    const float* ln1_b = (const float*)d_in[10];
    const float* ln2_g = (const float*)d_in[11];
    const float* ln2_b = (const float*)d_in[12];
    float* out = (float*)d_out;

    __half *q, *a, *bbuf, *w1, *w2, *w3, *w4;
    cudaGetSymbolAddress((void**)&q, g_q);
    cudaGetSymbolAddress((void**)&a, g_a);
    cudaGetSymbolAddress((void**)&bbuf, g_b);
    cudaGetSymbolAddress((void**)&w1, g_w1);
    cudaGetSymbolAddress((void**)&w2, g_w2);
    cudaGetSymbolAddress((void**)&w3, g_w3);
    cudaGetSymbolAddress((void**)&w4, g_w4);

    cudaFuncSetAttribute(attn_kernel, cudaFuncAttributeMaxDynamicSharedMemorySize, AT_SMEM);
    cudaFuncSetAttribute(tgemm_kernel<1>, cudaFuncAttributeMaxDynamicSharedMemorySize, TG_SMEM);
    cudaFuncSetAttribute(tgemm_kernel<2>, cudaFuncAttributeMaxDynamicSharedMemorySize, TG_SMEM);
    cudaFuncSetAttribute(tgemm_kernel<3>, cudaFuncAttributeMaxDynamicSharedMemorySize, TG_SMEM);

    const dim3 tb(32, 8);

    // 0) weight transpose -> fp16
    wconv_kernel<<<dim3(3 * DM / 32, DM / 32),  tb>>>(qkv_w, w1, DM,  3 * DM);
    wconv_kernel<<<dim3(DM / 32,     DM / 32),  tb>>>(out_w, w2, DM,  DM);
    wconv_kernel<<<dim3(FFH / 32,    DM / 32),  tb>>>(ff1_w, w3, DM,  FFH);
    wconv_kernel<<<dim3(DM / 32,     FFH / 32), tb>>>(ff2_w, w4, FFH, DM);

    // 1) bufA = LN1(x)  (fp16)
    ln_kernel<<<NROWS, 256>>>(x, ln1_g, ln1_b, a);

    // 2) qkv(fp16, q pre-scaled) = bufA @ qkv_w + qkv_b     [8192, 3072]
    tgemm_kernel<3><<<dim3(3 * DM / 128, NROWS / 128), 256, TG_SMEM>>>(
        a, w1, qkv_b, nullptr, nullptr, q, 3 * DM, DM);

    // 3) bufB = attention(qkv)  (fp16 ctx)
    attn_kernel<<<dim3(L_SEQ / 128, BATCH * NH), 256, AT_SMEM>>>(q, bbuf);

    // 4) out = x + bufB @ out_w + out_b                     [8192, 1024]
    tgemm_kernel<2><<<dim3(DM / 128, NROWS / 128), 256, TG_SMEM>>>(
        bbuf, w2, out_b, x, out, nullptr, DM, DM);

    // 5) bufA = LN2(out)
    ln_kernel<<<NROWS, 256>>>(out, ln2_g, ln2_b, a);

    // 6) bufB = GELU(bufA @ ff1_w + ff1_b)                  [8192, 2048]
    tgemm_kernel<1><<<dim3(FFH / 128, NROWS / 128), 256, TG_SMEM>>>(
        a, w3, ff1_b, nullptr, nullptr, bbuf, FFH, DM);

    // 7) out = out + bufB @ ff2_w + ff2_b                   [8192, 1024]
    tgemm_kernel<2><<<dim3(DM / 128, NROWS / 128), 256, TG_SMEM>>>(
        bbuf, w4, ff2_b, out, out, nullptr, DM, FFH);
}